// round 1
// baseline (speedup 1.0000x reference)
#include <cuda_runtime.h>
#include <math.h>

#define T_SEQ    2048
#define B_BATCH  2
#define DM       1024
#define NHEAD    16
#define HDIM     64
#define ROWS     (B_BATCH * T_SEQ)      // 4096
#define QKV_COLS (3 * DM)               // 3072

// Scratch (allocation-guard compliant: device globals)
__device__ float g_qkv[(size_t)ROWS * QKV_COLS];   // ~50 MB
__device__ float g_attn[(size_t)ROWS * DM];        // ~17 MB

// ---------------------------------------------------------------------------
// SGEMM: C[M,N] = A[M,K] @ B[K,N], fp32. 128x128x16 tile, 256 threads, 8x8/thread
// ---------------------------------------------------------------------------
#define GBM 128
#define GBN 128
#define GBK 16

__global__ __launch_bounds__(256) void sgemm_kernel(
    const float* __restrict__ A, const float* __restrict__ B,
    float* __restrict__ C, int M, int N, int K)
{
    __shared__ float As[GBK * 132];   // [k][m], padded
    __shared__ float Bs[GBK * 128];   // [k][n]

    const int tid = threadIdx.x;
    const int bm = blockIdx.y * GBM;
    const int bn = blockIdx.x * GBN;
    const int ty = tid >> 4, tx = tid & 15;
    const int row = ty * 8, col = tx * 8;

    float acc[8][8];
#pragma unroll
    for (int i = 0; i < 8; i++)
#pragma unroll
        for (int j = 0; j < 8; j++) acc[i][j] = 0.0f;

    for (int k0 = 0; k0 < K; k0 += GBK) {
#pragma unroll
        for (int u = 0; u < 2; u++) {
            int s = tid * 2 + u;
            // A: slot -> m = s/4, kq = (s%4)*4   (coalesced float4 along K)
            int m  = s >> 2;
            int kq = (s & 3) << 2;
            float4 a = *(const float4*)(A + (size_t)(bm + m) * K + k0 + kq);
            As[(kq + 0) * 132 + m] = a.x;
            As[(kq + 1) * 132 + m] = a.y;
            As[(kq + 2) * 132 + m] = a.z;
            As[(kq + 3) * 132 + m] = a.w;
            // B: slot -> k = s/32, nq = (s%32)*4
            int kk = s >> 5;
            int nq = (s & 31) << 2;
            *(float4*)&Bs[kk * 128 + nq] =
                *(const float4*)(B + (size_t)(k0 + kk) * N + bn + nq);
        }
        __syncthreads();

#pragma unroll
        for (int kk = 0; kk < GBK; kk++) {
            float4 a0 = *(float4*)&As[kk * 132 + row];
            float4 a1 = *(float4*)&As[kk * 132 + row + 4];
            float4 b0 = *(float4*)&Bs[kk * 128 + col];
            float4 b1 = *(float4*)&Bs[kk * 128 + col + 4];
            float ar[8] = {a0.x, a0.y, a0.z, a0.w, a1.x, a1.y, a1.z, a1.w};
            float br[8] = {b0.x, b0.y, b0.z, b0.w, b1.x, b1.y, b1.z, b1.w};
#pragma unroll
            for (int i = 0; i < 8; i++)
#pragma unroll
                for (int j = 0; j < 8; j++)
                    acc[i][j] += ar[i] * br[j];
        }
        __syncthreads();
    }

#pragma unroll
    for (int i = 0; i < 8; i++) {
        float* cp = C + (size_t)(bm + row + i) * N + bn + col;
        float4 o0 = {acc[i][0], acc[i][1], acc[i][2], acc[i][3]};
        float4 o1 = {acc[i][4], acc[i][5], acc[i][6], acc[i][7]};
        *(float4*)(cp)     = o0;
        *(float4*)(cp + 4) = o1;
    }
}

// ---------------------------------------------------------------------------
// RoPE (interleaved, in-place on q and k regions of g_qkv)
// result[2i]   = x[2i]*cos_i - x[2i+1]*sin_i
// result[2i+1] = x[2i+1]*cos_i + x[2i]*sin_i
// ---------------------------------------------------------------------------
__global__ void rope_kernel()
{
    int idx = blockIdx.x * blockDim.x + threadIdx.x;
    const int total = ROWS * NHEAD * (HDIM / 2);
    if (idx >= total) return;
    int i = idx & 31;          // pair index 0..31
    int h = (idx >> 5) & 15;   // head
    int r = idx >> 9;          // row 0..4095
    int t = r & (T_SEQ - 1);   // position

    double ang = (double)t * pow(10000.0, -(double)i / 32.0);
    float sn = (float)sin(ang);
    float cs = (float)cos(ang);

    float* base = g_qkv + (size_t)r * QKV_COLS + h * HDIM + 2 * i;
    // q
    {
        float x0 = base[0], x1 = base[1];
        base[0] = x0 * cs - x1 * sn;
        base[1] = x1 * cs + x0 * sn;
    }
    // k
    {
        float* kb = base + DM;
        float x0 = kb[0], x1 = kb[1];
        kb[0] = x0 * cs - x1 * sn;
        kb[1] = x1 * cs + x0 * sn;
    }
}

// ---------------------------------------------------------------------------
// Causal flash attention. Grid (16 qtiles, 16 heads, 2 batch). 256 threads.
// CTA: 128 q-rows, loops over 64-row K/V tiles. fp32 throughout.
// Thread (ty,tx): S rows m0=8*ty (8), S cols n0=4*tx (4), O cols c0=4*tx (4).
// ---------------------------------------------------------------------------
#define QS_STRIDE 132
#define KS_STRIDE 68
#define VS_STRIDE 68
#define PS_STRIDE 65
#define SMEM_FLOATS (64 * QS_STRIDE + 64 * KS_STRIDE + 64 * VS_STRIDE + 128 * PS_STRIDE)

__global__ __launch_bounds__(256) void flash_attn_kernel()
{
    extern __shared__ float smf[];
    float* Qs = smf;                       // [d][m]  64 x 132
    float* Ks = Qs + 64 * QS_STRIDE;       // [d][n]  64 x 68
    float* Vs = Ks + 64 * KS_STRIDE;       // [n][d]  64 x 68
    float* Ps = Vs + 64 * VS_STRIDE;       // [m][n] 128 x 65

    const int tid = threadIdx.x;
    const int ty = tid >> 4, tx = tid & 15;
    const int m0 = ty * 8, n0 = tx * 4, c0 = tx * 4;
    const int qi = (int)(gridDim.x - 1 - blockIdx.x);  // descending: long blocks first
    const int h = blockIdx.y, b = blockIdx.z;
    const int qbase = qi * 128;
    const size_t rowb = (size_t)b * T_SEQ;

    // Load Q tile (pre-scaled by 1/sqrt(Dh)=0.125), transposed to [d][m]
    {
        int m = tid >> 1;
        int d0 = (tid & 1) * 32;
        const float* src = g_qkv + (rowb + qbase + m) * QKV_COLS + h * HDIM + d0;
#pragma unroll
        for (int j = 0; j < 8; j++) {
            float4 v = *(const float4*)(src + 4 * j);
            int d = d0 + 4 * j;
            Qs[(d + 0) * QS_STRIDE + m] = v.x * 0.125f;
            Qs[(d + 1) * QS_STRIDE + m] = v.y * 0.125f;
            Qs[(d + 2) * QS_STRIDE + m] = v.z * 0.125f;
            Qs[(d + 3) * QS_STRIDE + m] = v.w * 0.125f;
        }
    }

    float Oacc[8][4];
    float mrow[8], lrow[8];
#pragma unroll
    for (int i = 0; i < 8; i++) {
        mrow[i] = -1e30f;
        lrow[i] = 0.0f;
#pragma unroll
        for (int j = 0; j < 4; j++) Oacc[i][j] = 0.0f;
    }

    const int nkt = qbase / 64 + 2;
    for (int kt = 0; kt < nkt; kt++) {
        const int kbase = kt * 64;
        __syncthreads();  // previous Ps/Vs consumers done; Qs ready (first iter)
        // Load K (transposed [d][n]) and V ([n][d]) tiles
        {
            int n = tid >> 2;
            int d0 = (tid & 3) * 16;
            const float* kp = g_qkv + (rowb + kbase + n) * QKV_COLS + DM + h * HDIM + d0;
            const float* vp = kp + DM;
#pragma unroll
            for (int j = 0; j < 4; j++) {
                int d = d0 + 4 * j;
                float4 kv = *(const float4*)(kp + 4 * j);
                Ks[(d + 0) * KS_STRIDE + n] = kv.x;
                Ks[(d + 1) * KS_STRIDE + n] = kv.y;
                Ks[(d + 2) * KS_STRIDE + n] = kv.z;
                Ks[(d + 3) * KS_STRIDE + n] = kv.w;
                float4 vv = *(const float4*)(vp + 4 * j);
                *(float4*)&Vs[n * VS_STRIDE + d] = vv;
            }
        }
        __syncthreads();

        // S = (Q * 1/8) @ K^T
        float s[8][4];
#pragma unroll
        for (int i = 0; i < 8; i++)
#pragma unroll
            for (int j = 0; j < 4; j++) s[i][j] = 0.0f;

#pragma unroll 8
        for (int d = 0; d < 64; d++) {
            float4 qa = *(float4*)&Qs[d * QS_STRIDE + m0];
            float4 qb = *(float4*)&Qs[d * QS_STRIDE + m0 + 4];
            float4 kk = *(float4*)&Ks[d * KS_STRIDE + n0];
            float qr[8] = {qa.x, qa.y, qa.z, qa.w, qb.x, qb.y, qb.z, qb.w};
            float kr[4] = {kk.x, kk.y, kk.z, kk.w};
#pragma unroll
            for (int i = 0; i < 8; i++)
#pragma unroll
                for (int j = 0; j < 4; j++)
                    s[i][j] += qr[i] * kr[j];
        }

        // Causal mask (only the last two k-tiles per q-tile need it)
        if (kbase + 63 > qbase) {
#pragma unroll
            for (int i = 0; i < 8; i++)
#pragma unroll
                for (int j = 0; j < 4; j++)
                    if (kbase + n0 + j > qbase + m0 + i) s[i][j] = -1e30f;
        }

        // Online softmax (row reductions across the 16 tx lanes)
#pragma unroll
        for (int i = 0; i < 8; i++) {
            float mx = fmaxf(fmaxf(s[i][0], s[i][1]), fmaxf(s[i][2], s[i][3]));
#pragma unroll
            for (int o = 8; o >= 1; o >>= 1)
                mx = fmaxf(mx, __shfl_xor_sync(0xffffffffu, mx, o));
            float newm = fmaxf(mrow[i], mx);
            float p0 = __expf(s[i][0] - newm);
            float p1 = __expf(s[i][1] - newm);
            float p2 = __expf(s[i][2] - newm);
            float p3 = __expf(s[i][3] - newm);
            float rs = (p0 + p1) + (p2 + p3);
#pragma unroll
            for (int o = 8; o >= 1; o >>= 1)
                rs += __shfl_xor_sync(0xffffffffu, rs, o);
            float alpha = __expf(mrow[i] - newm);
            lrow[i] = lrow[i] * alpha + rs;
            mrow[i] = newm;
#pragma unroll
            for (int j = 0; j < 4; j++) Oacc[i][j] *= alpha;
            Ps[(m0 + i) * PS_STRIDE + n0 + 0] = p0;
            Ps[(m0 + i) * PS_STRIDE + n0 + 1] = p1;
            Ps[(m0 + i) * PS_STRIDE + n0 + 2] = p2;
            Ps[(m0 + i) * PS_STRIDE + n0 + 3] = p3;
        }
        __syncthreads();

        // O += P @ V
#pragma unroll 4
        for (int n = 0; n < 64; n++) {
            float4 v = *(float4*)&Vs[n * VS_STRIDE + c0];
#pragma unroll
            for (int i = 0; i < 8; i++) {
                float p = Ps[(m0 + i) * PS_STRIDE + n];
                Oacc[i][0] += p * v.x;
                Oacc[i][1] += p * v.y;
                Oacc[i][2] += p * v.z;
                Oacc[i][3] += p * v.w;
            }
        }
    }

    // Normalize and store
#pragma unroll
    for (int i = 0; i < 8; i++) {
        float inv = 1.0f / lrow[i];
        float4 o = {Oacc[i][0] * inv, Oacc[i][1] * inv,
                    Oacc[i][2] * inv, Oacc[i][3] * inv};
        *(float4*)&g_attn[(rowb + qbase + m0 + i) * DM + h * HDIM + c0] = o;
    }
}

// ---------------------------------------------------------------------------
extern "C" void kernel_launch(void* const* d_in, const int* in_sizes, int n_in,
                              void* d_out, int out_size)
{
    const float* x    = (const float*)d_in[0];
    const float* Wqkv = (const float*)d_in[1];
    const float* Wout = (const float*)d_in[2];
    float* out = (float*)d_out;

    float* qkv  = nullptr;
    float* attn = nullptr;
    cudaGetSymbolAddress((void**)&qkv,  g_qkv);
    cudaGetSymbolAddress((void**)&attn, g_attn);

    // 1) QKV projection
    sgemm_kernel<<<dim3(QKV_COLS / GBN, ROWS / GBM), 256>>>(
        x, Wqkv, qkv, ROWS, QKV_COLS, DM);

    // 2) RoPE on q,k in-place
    {
        int total = ROWS * NHEAD * (HDIM / 2);
        rope_kernel<<<(total + 255) / 256, 256>>>();
    }

    // 3) Causal flash attention
    {
        static int smem_set = 0;
        if (!smem_set) {
            cudaFuncSetAttribute(flash_attn_kernel,
                                 cudaFuncAttributeMaxDynamicSharedMemorySize,
                                 SMEM_FLOATS * sizeof(float));
            smem_set = 1;
        }
        flash_attn_kernel<<<dim3(T_SEQ / 128, NHEAD, B_BATCH), 256,
                            SMEM_FLOATS * sizeof(float)>>>();
    }

    // 4) Output projection
    sgemm_kernel<<<dim3(DM / GBN, ROWS / GBM), 256>>>(
        attn, Wout, out, ROWS, DM, DM);
}

// round 3
// speedup vs baseline: 1.3661x; 1.3661x over previous
#include <cuda_runtime.h>
#include <cstdint>
#include <math.h>

#define T_SEQ    2048
#define B_BATCH  2
#define DM       1024
#define NHEAD    16
#define HDIM     64
#define ROWS     (B_BATCH * T_SEQ)      // 4096
#define QKV_COLS (3 * DM)               // 3072

// Scratch (allocation-guard compliant: device globals)
__device__ float g_qkv[(size_t)ROWS * QKV_COLS];     // ~50 MB
__device__ float g_attn[(size_t)ROWS * DM];          // ~17 MB
__device__ float g_WqkvT[(size_t)QKV_COLS * DM];     // 12 MB  [N][K]
__device__ float g_WoutT[(size_t)DM * DM];           // 4 MB   [N][K]

__device__ __forceinline__ uint32_t f2tf32(float x) {
    uint32_t r;
    asm("cvt.rna.tf32.f32 %0, %1;" : "=r"(r) : "f"(x));
    return r;
}

// ===========================================================================
// Weight transpose: src [R][C] row-major -> dst [C][R] row-major
// ===========================================================================
__global__ void transpose_kernel(const float* __restrict__ src,
                                 float* __restrict__ dst, int R, int C)
{
    __shared__ float tile[32][33];
    int c0 = blockIdx.x * 32, r0 = blockIdx.y * 32;
    int x = threadIdx.x, y = threadIdx.y;   // 32 x 8
#pragma unroll
    for (int i = 0; i < 32; i += 8)
        tile[y + i][x] = src[(size_t)(r0 + y + i) * C + c0 + x];
    __syncthreads();
#pragma unroll
    for (int i = 0; i < 32; i += 8)
        dst[(size_t)(c0 + y + i) * R + r0 + x] = tile[x][y + i];
}

// ===========================================================================
// TF32 mma.sync GEMM: C[M,N] = A[M,K] @ Bt[N,K]^T
// 128x128 block, BK=16, 256 threads (8 warps, 2x4), warp tile 64x32.
// mma.sync.aligned.m16n8k8.row.col.f32.tf32.tf32.f32
// Shared stride 20 -> conflict-free fragment loads, 16B-aligned float4 stores.
// ===========================================================================
#define SST 20   // smem row stride (floats)

__device__ __forceinline__ void mma_tf32(
    float* c, uint32_t a0, uint32_t a1, uint32_t a2, uint32_t a3,
    uint32_t b0, uint32_t b1)
{
    asm volatile(
        "mma.sync.aligned.m16n8k8.row.col.f32.tf32.tf32.f32 "
        "{%0,%1,%2,%3}, {%4,%5,%6,%7}, {%8,%9}, {%0,%1,%2,%3};"
        : "+f"(c[0]), "+f"(c[1]), "+f"(c[2]), "+f"(c[3])
        : "r"(a0), "r"(a1), "r"(a2), "r"(a3), "r"(b0), "r"(b1));
}

__global__ __launch_bounds__(256) void gemm_tf32(
    const float* __restrict__ A, const float* __restrict__ Bt,
    float* __restrict__ C, int M, int N, int K)
{
    __shared__ uint32_t As[2][128 * SST];
    __shared__ uint32_t Bs[2][128 * SST];

    const int tid  = threadIdx.x;
    const int lane = tid & 31;
    const int wid  = tid >> 5;
    const int wm   = (wid >> 2) * 64;    // warp row origin (0 / 64)
    const int wn   = (wid & 3) * 32;     // warp col origin (0/32/64/96)
    const int bm   = blockIdx.y * 128;
    const int bn   = blockIdx.x * 128;
    const int gid  = lane >> 2;          // group id 0..7
    const int tig  = lane & 3;           // thread-in-group 0..3

    float acc[4][4][4];
#pragma unroll
    for (int i = 0; i < 4; i++)
#pragma unroll
        for (int j = 0; j < 4; j++)
#pragma unroll
            for (int q = 0; q < 4; q++) acc[i][j][q] = 0.0f;

    const int r0 = tid >> 2,  c40 = (tid & 3);           // slot 0
    const int r1 = (tid + 256) >> 2, c41 = c40;          // slot 1 (same c4)

    float4 ra0, ra1, rb0, rb1;
    // prologue: load k-chunk 0
    ra0 = *(const float4*)(A  + (size_t)(bm + r0) * K + c40 * 4);
    ra1 = *(const float4*)(A  + (size_t)(bm + r1) * K + c41 * 4);
    rb0 = *(const float4*)(Bt + (size_t)(bn + r0) * K + c40 * 4);
    rb1 = *(const float4*)(Bt + (size_t)(bn + r1) * K + c41 * 4);

    const int niter = K >> 4;   // BK = 16
    int buf = 0;

    // store prologue
    {
        uint4 u;
        u.x = f2tf32(ra0.x); u.y = f2tf32(ra0.y); u.z = f2tf32(ra0.z); u.w = f2tf32(ra0.w);
        *(uint4*)&As[buf][r0 * SST + c40 * 4] = u;
        u.x = f2tf32(ra1.x); u.y = f2tf32(ra1.y); u.z = f2tf32(ra1.z); u.w = f2tf32(ra1.w);
        *(uint4*)&As[buf][r1 * SST + c41 * 4] = u;
        u.x = f2tf32(rb0.x); u.y = f2tf32(rb0.y); u.z = f2tf32(rb0.z); u.w = f2tf32(rb0.w);
        *(uint4*)&Bs[buf][r0 * SST + c40 * 4] = u;
        u.x = f2tf32(rb1.x); u.y = f2tf32(rb1.y); u.z = f2tf32(rb1.z); u.w = f2tf32(rb1.w);
        *(uint4*)&Bs[buf][r1 * SST + c41 * 4] = u;
    }
    __syncthreads();

    for (int it = 0; it < niter; it++) {
        const bool more = (it + 1) < niter;
        if (more) {
            const int k0 = (it + 1) << 4;
            ra0 = *(const float4*)(A  + (size_t)(bm + r0) * K + k0 + c40 * 4);
            ra1 = *(const float4*)(A  + (size_t)(bm + r1) * K + k0 + c41 * 4);
            rb0 = *(const float4*)(Bt + (size_t)(bn + r0) * K + k0 + c40 * 4);
            rb1 = *(const float4*)(Bt + (size_t)(bn + r1) * K + k0 + c41 * 4);
        }

        // compute on buf
#pragma unroll
        for (int ks = 0; ks < 16; ks += 8) {
            uint32_t afr[4][4], bfr[4][2];
#pragma unroll
            for (int mt = 0; mt < 4; mt++) {
                const int rb = wm + mt * 16;
                afr[mt][0] = As[buf][(rb + gid)     * SST + ks + tig];
                afr[mt][1] = As[buf][(rb + gid + 8) * SST + ks + tig];
                afr[mt][2] = As[buf][(rb + gid)     * SST + ks + tig + 4];
                afr[mt][3] = As[buf][(rb + gid + 8) * SST + ks + tig + 4];
            }
#pragma unroll
            for (int nt = 0; nt < 4; nt++) {
                const int nb = wn + nt * 8;
                bfr[nt][0] = Bs[buf][(nb + gid) * SST + ks + tig];
                bfr[nt][1] = Bs[buf][(nb + gid) * SST + ks + tig + 4];
            }
#pragma unroll
            for (int mt = 0; mt < 4; mt++)
#pragma unroll
                for (int nt = 0; nt < 4; nt++)
                    mma_tf32(acc[mt][nt], afr[mt][0], afr[mt][1], afr[mt][2],
                             afr[mt][3], bfr[nt][0], bfr[nt][1]);
        }

        if (more) {
            buf ^= 1;
            uint4 u;
            u.x = f2tf32(ra0.x); u.y = f2tf32(ra0.y); u.z = f2tf32(ra0.z); u.w = f2tf32(ra0.w);
            *(uint4*)&As[buf][r0 * SST + c40 * 4] = u;
            u.x = f2tf32(ra1.x); u.y = f2tf32(ra1.y); u.z = f2tf32(ra1.z); u.w = f2tf32(ra1.w);
            *(uint4*)&As[buf][r1 * SST + c41 * 4] = u;
            u.x = f2tf32(rb0.x); u.y = f2tf32(rb0.y); u.z = f2tf32(rb0.z); u.w = f2tf32(rb0.w);
            *(uint4*)&Bs[buf][r0 * SST + c40 * 4] = u;
            u.x = f2tf32(rb1.x); u.y = f2tf32(rb1.y); u.z = f2tf32(rb1.z); u.w = f2tf32(rb1.w);
            *(uint4*)&Bs[buf][r1 * SST + c41 * 4] = u;
            __syncthreads();
        }
    }

    // Epilogue: c0,c1 -> (row gid, cols 2*tig, 2*tig+1); c2,c3 -> row gid+8
#pragma unroll
    for (int mt = 0; mt < 4; mt++) {
        const int rb = bm + wm + mt * 16;
#pragma unroll
        for (int nt = 0; nt < 4; nt++) {
            const int cb = bn + wn + nt * 8 + 2 * tig;
            float2 lo = {acc[mt][nt][0], acc[mt][nt][1]};
            float2 hi = {acc[mt][nt][2], acc[mt][nt][3]};
            *(float2*)(C + (size_t)(rb + gid)     * N + cb) = lo;
            *(float2*)(C + (size_t)(rb + gid + 8) * N + cb) = hi;
        }
    }
}

// ===========================================================================
// RoPE (interleaved, in-place on q and k regions of g_qkv) — R1-proven
// ===========================================================================
__global__ void rope_kernel()
{
    int idx = blockIdx.x * blockDim.x + threadIdx.x;
    const int total = ROWS * NHEAD * (HDIM / 2);
    if (idx >= total) return;
    int i = idx & 31;          // pair index 0..31
    int h = (idx >> 5) & 15;   // head
    int r = idx >> 9;          // row 0..4095
    int t = r & (T_SEQ - 1);   // position

    double ang = (double)t * pow(10000.0, -(double)i / 32.0);
    float sn = (float)sin(ang);
    float cs = (float)cos(ang);

    float* base = g_qkv + (size_t)r * QKV_COLS + h * HDIM + 2 * i;
    {
        float x0 = base[0], x1 = base[1];
        base[0] = x0 * cs - x1 * sn;
        base[1] = x1 * cs + x0 * sn;
    }
    {
        float* kb = base + DM;
        float x0 = kb[0], x1 = kb[1];
        kb[0] = x0 * cs - x1 * sn;
        kb[1] = x1 * cs + x0 * sn;
    }
}

// ===========================================================================
// Causal flash attention (fp32) — R1-proven
// ===========================================================================
#define QS_STRIDE 132
#define KS_STRIDE 68
#define VS_STRIDE 68
#define PS_STRIDE 65
#define SMEM_FLOATS (64 * QS_STRIDE + 64 * KS_STRIDE + 64 * VS_STRIDE + 128 * PS_STRIDE)

__global__ __launch_bounds__(256) void flash_attn_kernel()
{
    extern __shared__ float smf[];
    float* Qs = smf;                       // [d][m]  64 x 132
    float* Ks = Qs + 64 * QS_STRIDE;       // [d][n]  64 x 68
    float* Vs = Ks + 64 * KS_STRIDE;       // [n][d]  64 x 68
    float* Ps = Vs + 64 * VS_STRIDE;       // [m][n] 128 x 65

    const int tid = threadIdx.x;
    const int ty = tid >> 4, tx = tid & 15;
    const int m0 = ty * 8, n0 = tx * 4, c0 = tx * 4;
    const int qi = (int)(gridDim.x - 1 - blockIdx.x);
    const int h = blockIdx.y, b = blockIdx.z;
    const int qbase = qi * 128;
    const size_t rowb = (size_t)b * T_SEQ;

    {
        int m = tid >> 1;
        int d0 = (tid & 1) * 32;
        const float* src = g_qkv + (rowb + qbase + m) * QKV_COLS + h * HDIM + d0;
#pragma unroll
        for (int j = 0; j < 8; j++) {
            float4 v = *(const float4*)(src + 4 * j);
            int d = d0 + 4 * j;
            Qs[(d + 0) * QS_STRIDE + m] = v.x * 0.125f;
            Qs[(d + 1) * QS_STRIDE + m] = v.y * 0.125f;
            Qs[(d + 2) * QS_STRIDE + m] = v.z * 0.125f;
            Qs[(d + 3) * QS_STRIDE + m] = v.w * 0.125f;
        }
    }

    float Oacc[8][4];
    float mrow[8], lrow[8];
#pragma unroll
    for (int i = 0; i < 8; i++) {
        mrow[i] = -1e30f;
        lrow[i] = 0.0f;
#pragma unroll
        for (int j = 0; j < 4; j++) Oacc[i][j] = 0.0f;
    }

    const int nkt = qbase / 64 + 2;
    for (int kt = 0; kt < nkt; kt++) {
        const int kbase = kt * 64;
        __syncthreads();
        {
            int n = tid >> 2;
            int d0 = (tid & 3) * 16;
            const float* kp = g_qkv + (rowb + kbase + n) * QKV_COLS + DM + h * HDIM + d0;
            const float* vp = kp + DM;
#pragma unroll
            for (int j = 0; j < 4; j++) {
                int d = d0 + 4 * j;
                float4 kv = *(const float4*)(kp + 4 * j);
                Ks[(d + 0) * KS_STRIDE + n] = kv.x;
                Ks[(d + 1) * KS_STRIDE + n] = kv.y;
                Ks[(d + 2) * KS_STRIDE + n] = kv.z;
                Ks[(d + 3) * KS_STRIDE + n] = kv.w;
                float4 vv = *(const float4*)(vp + 4 * j);
                *(float4*)&Vs[n * VS_STRIDE + d] = vv;
            }
        }
        __syncthreads();

        float s[8][4];
#pragma unroll
        for (int i = 0; i < 8; i++)
#pragma unroll
            for (int j = 0; j < 4; j++) s[i][j] = 0.0f;

#pragma unroll 8
        for (int d = 0; d < 64; d++) {
            float4 qa = *(float4*)&Qs[d * QS_STRIDE + m0];
            float4 qb = *(float4*)&Qs[d * QS_STRIDE + m0 + 4];
            float4 kk = *(float4*)&Ks[d * KS_STRIDE + n0];
            float qr[8] = {qa.x, qa.y, qa.z, qa.w, qb.x, qb.y, qb.z, qb.w};
            float kr[4] = {kk.x, kk.y, kk.z, kk.w};
#pragma unroll
            for (int i = 0; i < 8; i++)
#pragma unroll
                for (int j = 0; j < 4; j++)
                    s[i][j] += qr[i] * kr[j];
        }

        if (kbase + 63 > qbase) {
#pragma unroll
            for (int i = 0; i < 8; i++)
#pragma unroll
                for (int j = 0; j < 4; j++)
                    if (kbase + n0 + j > qbase + m0 + i) s[i][j] = -1e30f;
        }

#pragma unroll
        for (int i = 0; i < 8; i++) {
            float mx = fmaxf(fmaxf(s[i][0], s[i][1]), fmaxf(s[i][2], s[i][3]));
#pragma unroll
            for (int o = 8; o >= 1; o >>= 1)
                mx = fmaxf(mx, __shfl_xor_sync(0xffffffffu, mx, o));
            float newm = fmaxf(mrow[i], mx);
            float p0 = __expf(s[i][0] - newm);
            float p1 = __expf(s[i][1] - newm);
            float p2 = __expf(s[i][2] - newm);
            float p3 = __expf(s[i][3] - newm);
            float rs = (p0 + p1) + (p2 + p3);
#pragma unroll
            for (int o = 8; o >= 1; o >>= 1)
                rs += __shfl_xor_sync(0xffffffffu, rs, o);
            float alpha = __expf(mrow[i] - newm);
            lrow[i] = lrow[i] * alpha + rs;
            mrow[i] = newm;
#pragma unroll
            for (int j = 0; j < 4; j++) Oacc[i][j] *= alpha;
            Ps[(m0 + i) * PS_STRIDE + n0 + 0] = p0;
            Ps[(m0 + i) * PS_STRIDE + n0 + 1] = p1;
            Ps[(m0 + i) * PS_STRIDE + n0 + 2] = p2;
            Ps[(m0 + i) * PS_STRIDE + n0 + 3] = p3;
        }
        __syncthreads();

#pragma unroll 4
        for (int n = 0; n < 64; n++) {
            float4 v = *(float4*)&Vs[n * VS_STRIDE + c0];
#pragma unroll
            for (int i = 0; i < 8; i++) {
                float p = Ps[(m0 + i) * PS_STRIDE + n];
                Oacc[i][0] += p * v.x;
                Oacc[i][1] += p * v.y;
                Oacc[i][2] += p * v.z;
                Oacc[i][3] += p * v.w;
            }
        }
    }

#pragma unroll
    for (int i = 0; i < 8; i++) {
        float inv = 1.0f / lrow[i];
        float4 o = {Oacc[i][0] * inv, Oacc[i][1] * inv,
                    Oacc[i][2] * inv, Oacc[i][3] * inv};
        *(float4*)&g_attn[(rowb + qbase + m0 + i) * DM + h * HDIM + c0] = o;
    }
}

// ===========================================================================
extern "C" void kernel_launch(void* const* d_in, const int* in_sizes, int n_in,
                              void* d_out, int out_size)
{
    const float* x    = (const float*)d_in[0];
    const float* Wqkv = (const float*)d_in[1];
    const float* Wout = (const float*)d_in[2];
    float* out = (float*)d_out;

    float *qkv = nullptr, *attn = nullptr, *wqkvT = nullptr, *woutT = nullptr;
    cudaGetSymbolAddress((void**)&qkv,   g_qkv);
    cudaGetSymbolAddress((void**)&attn,  g_attn);
    cudaGetSymbolAddress((void**)&wqkvT, g_WqkvT);
    cudaGetSymbolAddress((void**)&woutT, g_WoutT);

    cudaFuncSetAttribute(flash_attn_kernel,
                         cudaFuncAttributeMaxDynamicSharedMemorySize,
                         SMEM_FLOATS * sizeof(float));

    // 0) Transpose weights to [N][K]
    transpose_kernel<<<dim3(QKV_COLS / 32, DM / 32), dim3(32, 8)>>>(
        Wqkv, wqkvT, DM, QKV_COLS);
    transpose_kernel<<<dim3(DM / 32, DM / 32), dim3(32, 8)>>>(
        Wout, woutT, DM, DM);

    // 1) QKV projection (tf32 mma.sync)
    gemm_tf32<<<dim3(QKV_COLS / 128, ROWS / 128), 256>>>(
        x, wqkvT, qkv, ROWS, QKV_COLS, DM);

    // 2) RoPE on q,k in-place
    {
        int total = ROWS * NHEAD * (HDIM / 2);
        rope_kernel<<<(total + 255) / 256, 256>>>();
    }

    // 3) Causal flash attention (fp32)
    flash_attn_kernel<<<dim3(T_SEQ / 128, NHEAD, B_BATCH), 256,
                        SMEM_FLOATS * sizeof(float)>>>();

    // 4) Output projection (tf32 mma.sync)
    gemm_tf32<<<dim3(DM / 128, ROWS / 128), 256>>>(
        attn, woutT, out, ROWS, DM, DM);
}

// round 4
// speedup vs baseline: 1.9593x; 1.4342x over previous
#include <cuda_runtime.h>
#include <cstdint>
#include <math.h>

#define T_SEQ    2048
#define B_BATCH  2
#define DM       1024
#define NHEAD    16
#define HDIM     64
#define ROWS     (B_BATCH * T_SEQ)      // 4096
#define QKV_COLS (3 * DM)               // 3072

// Scratch (allocation-guard compliant: device globals)
__device__ float g_qkv[(size_t)ROWS * QKV_COLS];     // ~50 MB
__device__ float g_attn[(size_t)ROWS * DM];          // ~17 MB
__device__ float g_WqkvT[(size_t)QKV_COLS * DM];     // 12 MB  [N][K]
__device__ float g_WoutT[(size_t)DM * DM];           // 4 MB   [N][K]
__device__ float g_rope_tab[(size_t)T_SEQ * 32 * 2]; // 512 KB (sin,cos)

__device__ __forceinline__ uint32_t f2tf32(float x) {
    uint32_t r;
    asm("cvt.rna.tf32.f32 %0, %1;" : "=r"(r) : "f"(x));
    return r;
}

// ===========================================================================
// Weight transpose: src [R][C] row-major -> dst [C][R] row-major
// ===========================================================================
__global__ void transpose_kernel(const float* __restrict__ src,
                                 float* __restrict__ dst, int R, int C)
{
    __shared__ float tile[32][33];
    int c0 = blockIdx.x * 32, r0 = blockIdx.y * 32;
    int x = threadIdx.x, y = threadIdx.y;   // 32 x 8
#pragma unroll
    for (int i = 0; i < 32; i += 8)
        tile[y + i][x] = src[(size_t)(r0 + y + i) * C + c0 + x];
    __syncthreads();
#pragma unroll
    for (int i = 0; i < 32; i += 8)
        dst[(size_t)(c0 + y + i) * R + r0 + x] = tile[x][y + i];
}

// ===========================================================================
// TF32 mma.sync GEMM: C[M,N] = A[M,K] @ Bt[N,K]^T   (R3-proven)
// 128x128 block, BK=16, 256 threads (8 warps, 2x4), warp tile 64x32.
// ===========================================================================
#define SST 20   // smem row stride (floats)

__device__ __forceinline__ void mma_tf32(
    float* c, uint32_t a0, uint32_t a1, uint32_t a2, uint32_t a3,
    uint32_t b0, uint32_t b1)
{
    asm volatile(
        "mma.sync.aligned.m16n8k8.row.col.f32.tf32.tf32.f32 "
        "{%0,%1,%2,%3}, {%4,%5,%6,%7}, {%8,%9}, {%0,%1,%2,%3};"
        : "+f"(c[0]), "+f"(c[1]), "+f"(c[2]), "+f"(c[3])
        : "r"(a0), "r"(a1), "r"(a2), "r"(a3), "r"(b0), "r"(b1));
}

__global__ __launch_bounds__(256) void gemm_tf32(
    const float* __restrict__ A, const float* __restrict__ Bt,
    float* __restrict__ C, int M, int N, int K)
{
    __shared__ uint32_t As[2][128 * SST];
    __shared__ uint32_t Bs[2][128 * SST];

    const int tid  = threadIdx.x;
    const int lane = tid & 31;
    const int wid  = tid >> 5;
    const int wm   = (wid >> 2) * 64;
    const int wn   = (wid & 3) * 32;
    const int bm   = blockIdx.y * 128;
    const int bn   = blockIdx.x * 128;
    const int gid  = lane >> 2;
    const int tig  = lane & 3;

    float acc[4][4][4];
#pragma unroll
    for (int i = 0; i < 4; i++)
#pragma unroll
        for (int j = 0; j < 4; j++)
#pragma unroll
            for (int q = 0; q < 4; q++) acc[i][j][q] = 0.0f;

    const int r0 = tid >> 2,  c40 = (tid & 3);
    const int r1 = (tid + 256) >> 2, c41 = c40;

    float4 ra0, ra1, rb0, rb1;
    ra0 = *(const float4*)(A  + (size_t)(bm + r0) * K + c40 * 4);
    ra1 = *(const float4*)(A  + (size_t)(bm + r1) * K + c41 * 4);
    rb0 = *(const float4*)(Bt + (size_t)(bn + r0) * K + c40 * 4);
    rb1 = *(const float4*)(Bt + (size_t)(bn + r1) * K + c41 * 4);

    const int niter = K >> 4;
    int buf = 0;

    {
        uint4 u;
        u.x = f2tf32(ra0.x); u.y = f2tf32(ra0.y); u.z = f2tf32(ra0.z); u.w = f2tf32(ra0.w);
        *(uint4*)&As[buf][r0 * SST + c40 * 4] = u;
        u.x = f2tf32(ra1.x); u.y = f2tf32(ra1.y); u.z = f2tf32(ra1.z); u.w = f2tf32(ra1.w);
        *(uint4*)&As[buf][r1 * SST + c41 * 4] = u;
        u.x = f2tf32(rb0.x); u.y = f2tf32(rb0.y); u.z = f2tf32(rb0.z); u.w = f2tf32(rb0.w);
        *(uint4*)&Bs[buf][r0 * SST + c40 * 4] = u;
        u.x = f2tf32(rb1.x); u.y = f2tf32(rb1.y); u.z = f2tf32(rb1.z); u.w = f2tf32(rb1.w);
        *(uint4*)&Bs[buf][r1 * SST + c41 * 4] = u;
    }
    __syncthreads();

    for (int it = 0; it < niter; it++) {
        const bool more = (it + 1) < niter;
        if (more) {
            const int k0 = (it + 1) << 4;
            ra0 = *(const float4*)(A  + (size_t)(bm + r0) * K + k0 + c40 * 4);
            ra1 = *(const float4*)(A  + (size_t)(bm + r1) * K + k0 + c41 * 4);
            rb0 = *(const float4*)(Bt + (size_t)(bn + r0) * K + k0 + c40 * 4);
            rb1 = *(const float4*)(Bt + (size_t)(bn + r1) * K + k0 + c41 * 4);
        }

#pragma unroll
        for (int ks = 0; ks < 16; ks += 8) {
            uint32_t afr[4][4], bfr[4][2];
#pragma unroll
            for (int mt = 0; mt < 4; mt++) {
                const int rb = wm + mt * 16;
                afr[mt][0] = As[buf][(rb + gid)     * SST + ks + tig];
                afr[mt][1] = As[buf][(rb + gid + 8) * SST + ks + tig];
                afr[mt][2] = As[buf][(rb + gid)     * SST + ks + tig + 4];
                afr[mt][3] = As[buf][(rb + gid + 8) * SST + ks + tig + 4];
            }
#pragma unroll
            for (int nt = 0; nt < 4; nt++) {
                const int nb = wn + nt * 8;
                bfr[nt][0] = Bs[buf][(nb + gid) * SST + ks + tig];
                bfr[nt][1] = Bs[buf][(nb + gid) * SST + ks + tig + 4];
            }
#pragma unroll
            for (int mt = 0; mt < 4; mt++)
#pragma unroll
                for (int nt = 0; nt < 4; nt++)
                    mma_tf32(acc[mt][nt], afr[mt][0], afr[mt][1], afr[mt][2],
                             afr[mt][3], bfr[nt][0], bfr[nt][1]);
        }

        if (more) {
            buf ^= 1;
            uint4 u;
            u.x = f2tf32(ra0.x); u.y = f2tf32(ra0.y); u.z = f2tf32(ra0.z); u.w = f2tf32(ra0.w);
            *(uint4*)&As[buf][r0 * SST + c40 * 4] = u;
            u.x = f2tf32(ra1.x); u.y = f2tf32(ra1.y); u.z = f2tf32(ra1.z); u.w = f2tf32(ra1.w);
            *(uint4*)&As[buf][r1 * SST + c41 * 4] = u;
            u.x = f2tf32(rb0.x); u.y = f2tf32(rb0.y); u.z = f2tf32(rb0.z); u.w = f2tf32(rb0.w);
            *(uint4*)&Bs[buf][r0 * SST + c40 * 4] = u;
            u.x = f2tf32(rb1.x); u.y = f2tf32(rb1.y); u.z = f2tf32(rb1.z); u.w = f2tf32(rb1.w);
            *(uint4*)&Bs[buf][r1 * SST + c41 * 4] = u;
            __syncthreads();
        }
    }

#pragma unroll
    for (int mt = 0; mt < 4; mt++) {
        const int rb = bm + wm + mt * 16;
#pragma unroll
        for (int nt = 0; nt < 4; nt++) {
            const int cb = bn + wn + nt * 8 + 2 * tig;
            float2 lo = {acc[mt][nt][0], acc[mt][nt][1]};
            float2 hi = {acc[mt][nt][2], acc[mt][nt][3]};
            *(float2*)(C + (size_t)(rb + gid)     * N + cb) = lo;
            *(float2*)(C + (size_t)(rb + gid + 8) * N + cb) = hi;
        }
    }
}

// ===========================================================================
// RoPE: precompute 2048x32 sin/cos table (double, exact same numerics as R3)
// then apply as a pure-memory pass.
// ===========================================================================
__global__ void rope_table_kernel()
{
    int idx = blockIdx.x * blockDim.x + threadIdx.x;   // 65536
    if (idx >= T_SEQ * 32) return;
    int i = idx & 31;
    int t = idx >> 5;
    double ang = (double)t * pow(10000.0, -(double)i / 32.0);
    g_rope_tab[2 * idx + 0] = (float)sin(ang);
    g_rope_tab[2 * idx + 1] = (float)cos(ang);
}

__global__ void rope_kernel()
{
    int idx = blockIdx.x * blockDim.x + threadIdx.x;
    const int total = ROWS * NHEAD * (HDIM / 2);
    if (idx >= total) return;
    int i = idx & 31;          // pair index 0..31
    int h = (idx >> 5) & 15;   // head
    int r = idx >> 9;          // row 0..4095
    int t = r & (T_SEQ - 1);   // position

    float sn = g_rope_tab[2 * (t * 32 + i) + 0];
    float cs = g_rope_tab[2 * (t * 32 + i) + 1];

    float* base = g_qkv + (size_t)r * QKV_COLS + h * HDIM + 2 * i;
    {
        float x0 = base[0], x1 = base[1];
        base[0] = x0 * cs - x1 * sn;
        base[1] = x1 * cs + x0 * sn;
    }
    {
        float* kb = base + DM;
        float x0 = kb[0], x1 = kb[1];
        kb[0] = x0 * cs - x1 * sn;
        kb[1] = x1 * cs + x0 * sn;
    }
}

// ===========================================================================
// Causal flash attention (fp32) — R1-proven
// ===========================================================================
#define QS_STRIDE 132
#define KS_STRIDE 68
#define VS_STRIDE 68
#define PS_STRIDE 65
#define SMEM_FLOATS (64 * QS_STRIDE + 64 * KS_STRIDE + 64 * VS_STRIDE + 128 * PS_STRIDE)

__global__ __launch_bounds__(256) void flash_attn_kernel()
{
    extern __shared__ float smf[];
    float* Qs = smf;                       // [d][m]  64 x 132
    float* Ks = Qs + 64 * QS_STRIDE;       // [d][n]  64 x 68
    float* Vs = Ks + 64 * KS_STRIDE;       // [n][d]  64 x 68
    float* Ps = Vs + 64 * VS_STRIDE;       // [m][n] 128 x 65

    const int tid = threadIdx.x;
    const int ty = tid >> 4, tx = tid & 15;
    const int m0 = ty * 8, n0 = tx * 4, c0 = tx * 4;
    const int qi = (int)(gridDim.x - 1 - blockIdx.x);
    const int h = blockIdx.y, b = blockIdx.z;
    const int qbase = qi * 128;
    const size_t rowb = (size_t)b * T_SEQ;

    {
        int m = tid >> 1;
        int d0 = (tid & 1) * 32;
        const float* src = g_qkv + (rowb + qbase + m) * QKV_COLS + h * HDIM + d0;
#pragma unroll
        for (int j = 0; j < 8; j++) {
            float4 v = *(const float4*)(src + 4 * j);
            int d = d0 + 4 * j;
            Qs[(d + 0) * QS_STRIDE + m] = v.x * 0.125f;
            Qs[(d + 1) * QS_STRIDE + m] = v.y * 0.125f;
            Qs[(d + 2) * QS_STRIDE + m] = v.z * 0.125f;
            Qs[(d + 3) * QS_STRIDE + m] = v.w * 0.125f;
        }
    }

    float Oacc[8][4];
    float mrow[8], lrow[8];
#pragma unroll
    for (int i = 0; i < 8; i++) {
        mrow[i] = -1e30f;
        lrow[i] = 0.0f;
#pragma unroll
        for (int j = 0; j < 4; j++) Oacc[i][j] = 0.0f;
    }

    const int nkt = qbase / 64 + 2;
    for (int kt = 0; kt < nkt; kt++) {
        const int kbase = kt * 64;
        __syncthreads();
        {
            int n = tid >> 2;
            int d0 = (tid & 3) * 16;
            const float* kp = g_qkv + (rowb + kbase + n) * QKV_COLS + DM + h * HDIM + d0;
            const float* vp = kp + DM;
#pragma unroll
            for (int j = 0; j < 4; j++) {
                int d = d0 + 4 * j;
                float4 kv = *(const float4*)(kp + 4 * j);
                Ks[(d + 0) * KS_STRIDE + n] = kv.x;
                Ks[(d + 1) * KS_STRIDE + n] = kv.y;
                Ks[(d + 2) * KS_STRIDE + n] = kv.z;
                Ks[(d + 3) * KS_STRIDE + n] = kv.w;
                float4 vv = *(const float4*)(vp + 4 * j);
                *(float4*)&Vs[n * VS_STRIDE + d] = vv;
            }
        }
        __syncthreads();

        float s[8][4];
#pragma unroll
        for (int i = 0; i < 8; i++)
#pragma unroll
            for (int j = 0; j < 4; j++) s[i][j] = 0.0f;

#pragma unroll 8
        for (int d = 0; d < 64; d++) {
            float4 qa = *(float4*)&Qs[d * QS_STRIDE + m0];
            float4 qb = *(float4*)&Qs[d * QS_STRIDE + m0 + 4];
            float4 kk = *(float4*)&Ks[d * KS_STRIDE + n0];
            float qr[8] = {qa.x, qa.y, qa.z, qa.w, qb.x, qb.y, qb.z, qb.w};
            float kr[4] = {kk.x, kk.y, kk.z, kk.w};
#pragma unroll
            for (int i = 0; i < 8; i++)
#pragma unroll
                for (int j = 0; j < 4; j++)
                    s[i][j] += qr[i] * kr[j];
        }

        if (kbase + 63 > qbase) {
#pragma unroll
            for (int i = 0; i < 8; i++)
#pragma unroll
                for (int j = 0; j < 4; j++)
                    if (kbase + n0 + j > qbase + m0 + i) s[i][j] = -1e30f;
        }

#pragma unroll
        for (int i = 0; i < 8; i++) {
            float mx = fmaxf(fmaxf(s[i][0], s[i][1]), fmaxf(s[i][2], s[i][3]));
#pragma unroll
            for (int o = 8; o >= 1; o >>= 1)
                mx = fmaxf(mx, __shfl_xor_sync(0xffffffffu, mx, o));
            float newm = fmaxf(mrow[i], mx);
            float p0 = __expf(s[i][0] - newm);
            float p1 = __expf(s[i][1] - newm);
            float p2 = __expf(s[i][2] - newm);
            float p3 = __expf(s[i][3] - newm);
            float rs = (p0 + p1) + (p2 + p3);
#pragma unroll
            for (int o = 8; o >= 1; o >>= 1)
                rs += __shfl_xor_sync(0xffffffffu, rs, o);
            float alpha = __expf(mrow[i] - newm);
            lrow[i] = lrow[i] * alpha + rs;
            mrow[i] = newm;
#pragma unroll
            for (int j = 0; j < 4; j++) Oacc[i][j] *= alpha;
            Ps[(m0 + i) * PS_STRIDE + n0 + 0] = p0;
            Ps[(m0 + i) * PS_STRIDE + n0 + 1] = p1;
            Ps[(m0 + i) * PS_STRIDE + n0 + 2] = p2;
            Ps[(m0 + i) * PS_STRIDE + n0 + 3] = p3;
        }
        __syncthreads();

#pragma unroll 4
        for (int n = 0; n < 64; n++) {
            float4 v = *(float4*)&Vs[n * VS_STRIDE + c0];
#pragma unroll
            for (int i = 0; i < 8; i++) {
                float p = Ps[(m0 + i) * PS_STRIDE + n];
                Oacc[i][0] += p * v.x;
                Oacc[i][1] += p * v.y;
                Oacc[i][2] += p * v.z;
                Oacc[i][3] += p * v.w;
            }
        }
    }

#pragma unroll
    for (int i = 0; i < 8; i++) {
        float inv = 1.0f / lrow[i];
        float4 o = {Oacc[i][0] * inv, Oacc[i][1] * inv,
                    Oacc[i][2] * inv, Oacc[i][3] * inv};
        *(float4*)&g_attn[(rowb + qbase + m0 + i) * DM + h * HDIM + c0] = o;
    }
}

// ===========================================================================
extern "C" void kernel_launch(void* const* d_in, const int* in_sizes, int n_in,
                              void* d_out, int out_size)
{
    const float* x    = (const float*)d_in[0];
    const float* Wqkv = (const float*)d_in[1];
    const float* Wout = (const float*)d_in[2];
    float* out = (float*)d_out;

    float *qkv = nullptr, *attn = nullptr, *wqkvT = nullptr, *woutT = nullptr;
    cudaGetSymbolAddress((void**)&qkv,   g_qkv);
    cudaGetSymbolAddress((void**)&attn,  g_attn);
    cudaGetSymbolAddress((void**)&wqkvT, g_WqkvT);
    cudaGetSymbolAddress((void**)&woutT, g_WoutT);

    cudaFuncSetAttribute(flash_attn_kernel,
                         cudaFuncAttributeMaxDynamicSharedMemorySize,
                         SMEM_FLOATS * sizeof(float));

    // 0) RoPE table (overlaps conceptually with transposes/GEMM)
    rope_table_kernel<<<(T_SEQ * 32 + 255) / 256, 256>>>();

    // 0b) Transpose weights to [N][K]
    transpose_kernel<<<dim3(QKV_COLS / 32, DM / 32), dim3(32, 8)>>>(
        Wqkv, wqkvT, DM, QKV_COLS);
    transpose_kernel<<<dim3(DM / 32, DM / 32), dim3(32, 8)>>>(
        Wout, woutT, DM, DM);

    // 1) QKV projection (tf32 mma.sync)
    gemm_tf32<<<dim3(QKV_COLS / 128, ROWS / 128), 256>>>(
        x, wqkvT, qkv, ROWS, QKV_COLS, DM);

    // 2) RoPE on q,k in-place (table lookup)
    {
        int total = ROWS * NHEAD * (HDIM / 2);
        rope_kernel<<<(total + 255) / 256, 256>>>();
    }

    // 3) Causal flash attention (fp32)
    flash_attn_kernel<<<dim3(T_SEQ / 128, NHEAD, B_BATCH), 256,
                        SMEM_FLOATS * sizeof(float)>>>();

    // 4) Output projection (tf32 mma.sync)
    gemm_tf32<<<dim3(DM / 128, ROWS / 128), 256>>>(
        attn, woutT, out, ROWS, DM, DM);
}

// round 5
// speedup vs baseline: 3.1647x; 1.6153x over previous
#include <cuda_runtime.h>
#include <cstdint>
#include <math.h>

#define T_SEQ    2048
#define B_BATCH  2
#define DM       1024
#define NHEAD    16
#define HDIM     64
#define ROWS     (B_BATCH * T_SEQ)      // 4096
#define QKV_COLS (3 * DM)               // 3072

// Scratch (allocation-guard compliant: device globals)
__device__ float g_qkv[(size_t)ROWS * QKV_COLS];     // ~50 MB
__device__ float g_attn[(size_t)ROWS * DM];          // ~17 MB
__device__ float g_WqkvT[(size_t)QKV_COLS * DM];     // 12 MB  [N][K]
__device__ float g_WoutT[(size_t)DM * DM];           // 4 MB   [N][K]
__device__ float g_rope_tab[(size_t)T_SEQ * 32 * 2]; // 512 KB (sin,cos)

__device__ __forceinline__ uint32_t f2tf32(float x) {
    uint32_t r;
    asm("cvt.rna.tf32.f32 %0, %1;" : "=r"(r) : "f"(x));
    return r;
}

__device__ __forceinline__ void mma_tf32(
    float* c, uint32_t a0, uint32_t a1, uint32_t a2, uint32_t a3,
    uint32_t b0, uint32_t b1)
{
    asm volatile(
        "mma.sync.aligned.m16n8k8.row.col.f32.tf32.tf32.f32 "
        "{%0,%1,%2,%3}, {%4,%5,%6,%7}, {%8,%9}, {%0,%1,%2,%3};"
        : "+f"(c[0]), "+f"(c[1]), "+f"(c[2]), "+f"(c[3])
        : "r"(a0), "r"(a1), "r"(a2), "r"(a3), "r"(b0), "r"(b1));
}

// ===========================================================================
// Weight transpose: src [R][C] row-major -> dst [C][R] row-major
// ===========================================================================
__global__ void transpose_kernel(const float* __restrict__ src,
                                 float* __restrict__ dst, int R, int C)
{
    __shared__ float tile[32][33];
    int c0 = blockIdx.x * 32, r0 = blockIdx.y * 32;
    int x = threadIdx.x, y = threadIdx.y;   // 32 x 8
#pragma unroll
    for (int i = 0; i < 32; i += 8)
        tile[y + i][x] = src[(size_t)(r0 + y + i) * C + c0 + x];
    __syncthreads();
#pragma unroll
    for (int i = 0; i < 32; i += 8)
        dst[(size_t)(c0 + y + i) * R + r0 + x] = tile[x][y + i];
}

// ===========================================================================
// TF32 mma.sync GEMM: C[M,N] = A[M,K] @ Bt[N,K]^T   (R3-proven)
// ===========================================================================
#define SST 20   // smem row stride (floats)

__global__ __launch_bounds__(256) void gemm_tf32(
    const float* __restrict__ A, const float* __restrict__ Bt,
    float* __restrict__ C, int M, int N, int K)
{
    __shared__ uint32_t As[2][128 * SST];
    __shared__ uint32_t Bs[2][128 * SST];

    const int tid  = threadIdx.x;
    const int lane = tid & 31;
    const int wid  = tid >> 5;
    const int wm   = (wid >> 2) * 64;
    const int wn   = (wid & 3) * 32;
    const int bm   = blockIdx.y * 128;
    const int bn   = blockIdx.x * 128;
    const int gid  = lane >> 2;
    const int tig  = lane & 3;

    float acc[4][4][4];
#pragma unroll
    for (int i = 0; i < 4; i++)
#pragma unroll
        for (int j = 0; j < 4; j++)
#pragma unroll
            for (int q = 0; q < 4; q++) acc[i][j][q] = 0.0f;

    const int r0 = tid >> 2,  c40 = (tid & 3);
    const int r1 = (tid + 256) >> 2, c41 = c40;

    float4 ra0, ra1, rb0, rb1;
    ra0 = *(const float4*)(A  + (size_t)(bm + r0) * K + c40 * 4);
    ra1 = *(const float4*)(A  + (size_t)(bm + r1) * K + c41 * 4);
    rb0 = *(const float4*)(Bt + (size_t)(bn + r0) * K + c40 * 4);
    rb1 = *(const float4*)(Bt + (size_t)(bn + r1) * K + c41 * 4);

    const int niter = K >> 4;
    int buf = 0;

    {
        uint4 u;
        u.x = f2tf32(ra0.x); u.y = f2tf32(ra0.y); u.z = f2tf32(ra0.z); u.w = f2tf32(ra0.w);
        *(uint4*)&As[buf][r0 * SST + c40 * 4] = u;
        u.x = f2tf32(ra1.x); u.y = f2tf32(ra1.y); u.z = f2tf32(ra1.z); u.w = f2tf32(ra1.w);
        *(uint4*)&As[buf][r1 * SST + c41 * 4] = u;
        u.x = f2tf32(rb0.x); u.y = f2tf32(rb0.y); u.z = f2tf32(rb0.z); u.w = f2tf32(rb0.w);
        *(uint4*)&Bs[buf][r0 * SST + c40 * 4] = u;
        u.x = f2tf32(rb1.x); u.y = f2tf32(rb1.y); u.z = f2tf32(rb1.z); u.w = f2tf32(rb1.w);
        *(uint4*)&Bs[buf][r1 * SST + c41 * 4] = u;
    }
    __syncthreads();

    for (int it = 0; it < niter; it++) {
        const bool more = (it + 1) < niter;
        if (more) {
            const int k0 = (it + 1) << 4;
            ra0 = *(const float4*)(A  + (size_t)(bm + r0) * K + k0 + c40 * 4);
            ra1 = *(const float4*)(A  + (size_t)(bm + r1) * K + k0 + c41 * 4);
            rb0 = *(const float4*)(Bt + (size_t)(bn + r0) * K + k0 + c40 * 4);
            rb1 = *(const float4*)(Bt + (size_t)(bn + r1) * K + k0 + c41 * 4);
        }

#pragma unroll
        for (int ks = 0; ks < 16; ks += 8) {
            uint32_t afr[4][4], bfr[4][2];
#pragma unroll
            for (int mt = 0; mt < 4; mt++) {
                const int rb = wm + mt * 16;
                afr[mt][0] = As[buf][(rb + gid)     * SST + ks + tig];
                afr[mt][1] = As[buf][(rb + gid + 8) * SST + ks + tig];
                afr[mt][2] = As[buf][(rb + gid)     * SST + ks + tig + 4];
                afr[mt][3] = As[buf][(rb + gid + 8) * SST + ks + tig + 4];
            }
#pragma unroll
            for (int nt = 0; nt < 4; nt++) {
                const int nb = wn + nt * 8;
                bfr[nt][0] = Bs[buf][(nb + gid) * SST + ks + tig];
                bfr[nt][1] = Bs[buf][(nb + gid) * SST + ks + tig + 4];
            }
#pragma unroll
            for (int mt = 0; mt < 4; mt++)
#pragma unroll
                for (int nt = 0; nt < 4; nt++)
                    mma_tf32(acc[mt][nt], afr[mt][0], afr[mt][1], afr[mt][2],
                             afr[mt][3], bfr[nt][0], bfr[nt][1]);
        }

        if (more) {
            buf ^= 1;
            uint4 u;
            u.x = f2tf32(ra0.x); u.y = f2tf32(ra0.y); u.z = f2tf32(ra0.z); u.w = f2tf32(ra0.w);
            *(uint4*)&As[buf][r0 * SST + c40 * 4] = u;
            u.x = f2tf32(ra1.x); u.y = f2tf32(ra1.y); u.z = f2tf32(ra1.z); u.w = f2tf32(ra1.w);
            *(uint4*)&As[buf][r1 * SST + c41 * 4] = u;
            u.x = f2tf32(rb0.x); u.y = f2tf32(rb0.y); u.z = f2tf32(rb0.z); u.w = f2tf32(rb0.w);
            *(uint4*)&Bs[buf][r0 * SST + c40 * 4] = u;
            u.x = f2tf32(rb1.x); u.y = f2tf32(rb1.y); u.z = f2tf32(rb1.z); u.w = f2tf32(rb1.w);
            *(uint4*)&Bs[buf][r1 * SST + c41 * 4] = u;
            __syncthreads();
        }
    }

#pragma unroll
    for (int mt = 0; mt < 4; mt++) {
        const int rb = bm + wm + mt * 16;
#pragma unroll
        for (int nt = 0; nt < 4; nt++) {
            const int cb = bn + wn + nt * 8 + 2 * tig;
            float2 lo = {acc[mt][nt][0], acc[mt][nt][1]};
            float2 hi = {acc[mt][nt][2], acc[mt][nt][3]};
            *(float2*)(C + (size_t)(rb + gid)     * N + cb) = lo;
            *(float2*)(C + (size_t)(rb + gid + 8) * N + cb) = hi;
        }
    }
}

// ===========================================================================
// RoPE table + apply (R4-proven)
// ===========================================================================
__global__ void rope_table_kernel()
{
    int idx = blockIdx.x * blockDim.x + threadIdx.x;   // 65536
    if (idx >= T_SEQ * 32) return;
    int i = idx & 31;
    int t = idx >> 5;
    double ang = (double)t * pow(10000.0, -(double)i / 32.0);
    g_rope_tab[2 * idx + 0] = (float)sin(ang);
    g_rope_tab[2 * idx + 1] = (float)cos(ang);
}

__global__ void rope_kernel()
{
    int idx = blockIdx.x * blockDim.x + threadIdx.x;
    const int total = ROWS * NHEAD * (HDIM / 2);
    if (idx >= total) return;
    int i = idx & 31;
    int h = (idx >> 5) & 15;
    int r = idx >> 9;
    int t = r & (T_SEQ - 1);

    float sn = g_rope_tab[2 * (t * 32 + i) + 0];
    float cs = g_rope_tab[2 * (t * 32 + i) + 1];

    float* base = g_qkv + (size_t)r * QKV_COLS + h * HDIM + 2 * i;
    {
        float x0 = base[0], x1 = base[1];
        base[0] = x0 * cs - x1 * sn;
        base[1] = x1 * cs + x0 * sn;
    }
    {
        float* kb = base + DM;
        float x0 = kb[0], x1 = kb[1];
        kb[0] = x0 * cs - x1 * sn;
        kb[1] = x1 * cs + x0 * sn;
    }
}

// ===========================================================================
// Tensor-core causal flash attention (tf32 mma.sync).
// Grid (16 qtiles, 16 heads, 2 batch), 256 threads = 8 warps.
// Warp w owns q-rows [16w, 16w+16). KV tiles of 64 keys.
// All smem stride 72 (== 8 mod 32): conflict-free frag loads.
// ===========================================================================
#define SAT 72
#define FA_SMEM ((64 * SAT + 64 * SAT + 128 * SAT) * 4)   // K + V + P(=Q stage)

__global__ __launch_bounds__(256) void flash_attn_tc()
{
    extern __shared__ uint32_t smu[];
    uint32_t* Ksm = smu;                   // [key][d]   64 x 72
    uint32_t* Vsm = Ksm + 64 * SAT;        // [key][d]   64 x 72
    uint32_t* Psm = Vsm + 64 * SAT;        // [m][key]  128 x 72 (Q staging first)

    const int tid  = threadIdx.x;
    const int lane = tid & 31;
    const int wid  = tid >> 5;
    const int gid  = lane >> 2;
    const int tig  = lane & 3;
    const int qi = (int)(gridDim.x - 1 - blockIdx.x);
    const int h = blockIdx.y, b = blockIdx.z;
    const int qbase = qi * 128;
    const size_t rowb = (size_t)b * T_SEQ;
    const int wrow = 16 * wid;             // warp row origin in tile

    // ---- stage Q (scaled by 1/8, tf32) into Psm ----
    {
        int m = tid >> 1;
        int d0 = (tid & 1) * 32;
        const float* src = g_qkv + (rowb + qbase + m) * QKV_COLS + h * HDIM + d0;
#pragma unroll
        for (int j = 0; j < 8; j++) {
            float4 v = *(const float4*)(src + 4 * j);
            uint32_t* dst = &Psm[m * SAT + d0 + 4 * j];
            dst[0] = f2tf32(v.x * 0.125f);
            dst[1] = f2tf32(v.y * 0.125f);
            dst[2] = f2tf32(v.z * 0.125f);
            dst[3] = f2tf32(v.w * 0.125f);
        }
    }
    __syncthreads();

    // ---- hoist Q fragments to registers (reused across all KV tiles) ----
    uint32_t qf[8][4];
#pragma unroll
    for (int ks = 0; ks < 8; ks++) {
        qf[ks][0] = Psm[(wrow + gid)     * SAT + ks * 8 + tig];
        qf[ks][1] = Psm[(wrow + gid + 8) * SAT + ks * 8 + tig];
        qf[ks][2] = Psm[(wrow + gid)     * SAT + ks * 8 + tig + 4];
        qf[ks][3] = Psm[(wrow + gid + 8) * SAT + ks * 8 + tig + 4];
    }

    float Oacc[8][4];
#pragma unroll
    for (int nt = 0; nt < 8; nt++)
#pragma unroll
        for (int q = 0; q < 4; q++) Oacc[nt][q] = 0.0f;
    float mrow0 = -1e30f, mrow1 = -1e30f, lrow0 = 0.0f, lrow1 = 0.0f;

    const int nkt = qbase / 64 + 2;
    for (int kt = 0; kt < nkt; kt++) {
        const int kbase = kt * 64;
        __syncthreads();   // prev iter's K/V consumers done
        // ---- load K,V tile (tf32) ----
        {
            int n  = tid >> 2;
            int d0 = (tid & 3) * 16;
            const float* kp = g_qkv + (rowb + kbase + n) * QKV_COLS + DM + h * HDIM + d0;
            const float* vp = kp + DM;
#pragma unroll
            for (int j = 0; j < 4; j++) {
                float4 kv = *(const float4*)(kp + 4 * j);
                uint32_t* kd = &Ksm[n * SAT + d0 + 4 * j];
                kd[0] = f2tf32(kv.x); kd[1] = f2tf32(kv.y);
                kd[2] = f2tf32(kv.z); kd[3] = f2tf32(kv.w);
                float4 vv = *(const float4*)(vp + 4 * j);
                uint32_t* vd = &Vsm[n * SAT + d0 + 4 * j];
                vd[0] = f2tf32(vv.x); vd[1] = f2tf32(vv.y);
                vd[2] = f2tf32(vv.z); vd[3] = f2tf32(vv.w);
            }
        }
        __syncthreads();

        // ---- S = Q @ K^T  (16 x 64 per warp) ----
        float sacc[8][4];
#pragma unroll
        for (int nt = 0; nt < 8; nt++)
#pragma unroll
            for (int q = 0; q < 4; q++) sacc[nt][q] = 0.0f;

#pragma unroll
        for (int ks = 0; ks < 8; ks++) {
#pragma unroll
            for (int nt = 0; nt < 8; nt++) {
                uint32_t b0 = Ksm[(nt * 8 + gid) * SAT + ks * 8 + tig];
                uint32_t b1 = Ksm[(nt * 8 + gid) * SAT + ks * 8 + tig + 4];
                mma_tf32(sacc[nt], qf[ks][0], qf[ks][1], qf[ks][2], qf[ks][3],
                         b0, b1);
            }
        }

        // ---- causal mask (last two tiles only) ----
        const int r0g = qbase + wrow + gid;
        if (kbase + 63 > qbase) {
#pragma unroll
            for (int nt = 0; nt < 8; nt++) {
                int col = kbase + nt * 8 + 2 * tig;
                if (col     > r0g)     sacc[nt][0] = -1e30f;
                if (col + 1 > r0g)     sacc[nt][1] = -1e30f;
                if (col     > r0g + 8) sacc[nt][2] = -1e30f;
                if (col + 1 > r0g + 8) sacc[nt][3] = -1e30f;
            }
        }

        // ---- online softmax (quad reductions) ----
        float mx0 = -1e30f, mx1 = -1e30f;
#pragma unroll
        for (int nt = 0; nt < 8; nt++) {
            mx0 = fmaxf(mx0, fmaxf(sacc[nt][0], sacc[nt][1]));
            mx1 = fmaxf(mx1, fmaxf(sacc[nt][2], sacc[nt][3]));
        }
        mx0 = fmaxf(mx0, __shfl_xor_sync(0xffffffffu, mx0, 1));
        mx0 = fmaxf(mx0, __shfl_xor_sync(0xffffffffu, mx0, 2));
        mx1 = fmaxf(mx1, __shfl_xor_sync(0xffffffffu, mx1, 1));
        mx1 = fmaxf(mx1, __shfl_xor_sync(0xffffffffu, mx1, 2));
        const float nm0 = fmaxf(mrow0, mx0);
        const float nm1 = fmaxf(mrow1, mx1);

        float sum0 = 0.0f, sum1 = 0.0f;
#pragma unroll
        for (int nt = 0; nt < 8; nt++) {
            float p00 = __expf(sacc[nt][0] - nm0);
            float p01 = __expf(sacc[nt][1] - nm0);
            float p10 = __expf(sacc[nt][2] - nm1);
            float p11 = __expf(sacc[nt][3] - nm1);
            sum0 += p00 + p01;
            sum1 += p10 + p11;
            uint2 u0 = {f2tf32(p00), f2tf32(p01)};
            uint2 u1 = {f2tf32(p10), f2tf32(p11)};
            *(uint2*)&Psm[(wrow + gid)     * SAT + nt * 8 + 2 * tig] = u0;
            *(uint2*)&Psm[(wrow + gid + 8) * SAT + nt * 8 + 2 * tig] = u1;
        }
        sum0 += __shfl_xor_sync(0xffffffffu, sum0, 1);
        sum0 += __shfl_xor_sync(0xffffffffu, sum0, 2);
        sum1 += __shfl_xor_sync(0xffffffffu, sum1, 1);
        sum1 += __shfl_xor_sync(0xffffffffu, sum1, 2);

        const float a0 = __expf(mrow0 - nm0);
        const float a1 = __expf(mrow1 - nm1);
        lrow0 = lrow0 * a0 + sum0;
        lrow1 = lrow1 * a1 + sum1;
        mrow0 = nm0; mrow1 = nm1;
#pragma unroll
        for (int nt = 0; nt < 8; nt++) {
            Oacc[nt][0] *= a0; Oacc[nt][1] *= a0;
            Oacc[nt][2] *= a1; Oacc[nt][3] *= a1;
        }
        __syncwarp();   // make P stores visible to frag loads within warp

        // ---- O += P @ V  (16 x 64 per warp, K = 64 keys) ----
#pragma unroll
        for (int ks = 0; ks < 8; ks++) {
            uint32_t a0f = Psm[(wrow + gid)     * SAT + ks * 8 + tig];
            uint32_t a1f = Psm[(wrow + gid + 8) * SAT + ks * 8 + tig];
            uint32_t a2f = Psm[(wrow + gid)     * SAT + ks * 8 + tig + 4];
            uint32_t a3f = Psm[(wrow + gid + 8) * SAT + ks * 8 + tig + 4];
#pragma unroll
            for (int nt = 0; nt < 8; nt++) {
                uint32_t b0 = Vsm[(ks * 8 + tig)     * SAT + nt * 8 + gid];
                uint32_t b1 = Vsm[(ks * 8 + tig + 4) * SAT + nt * 8 + gid];
                mma_tf32(Oacc[nt], a0f, a1f, a2f, a3f, b0, b1);
            }
        }
    }

    // ---- normalize + store ----
    const float i0 = 1.0f / lrow0;
    const float i1 = 1.0f / lrow1;
    const int r0g = qbase + wrow + gid;
#pragma unroll
    for (int nt = 0; nt < 8; nt++) {
        const int c = h * HDIM + nt * 8 + 2 * tig;
        float2 lo = {Oacc[nt][0] * i0, Oacc[nt][1] * i0};
        float2 hi = {Oacc[nt][2] * i1, Oacc[nt][3] * i1};
        *(float2*)&g_attn[(rowb + r0g)     * DM + c] = lo;
        *(float2*)&g_attn[(rowb + r0g + 8) * DM + c] = hi;
    }
}

// ===========================================================================
extern "C" void kernel_launch(void* const* d_in, const int* in_sizes, int n_in,
                              void* d_out, int out_size)
{
    const float* x    = (const float*)d_in[0];
    const float* Wqkv = (const float*)d_in[1];
    const float* Wout = (const float*)d_in[2];
    float* out = (float*)d_out;

    float *qkv = nullptr, *attn = nullptr, *wqkvT = nullptr, *woutT = nullptr;
    cudaGetSymbolAddress((void**)&qkv,   g_qkv);
    cudaGetSymbolAddress((void**)&attn,  g_attn);
    cudaGetSymbolAddress((void**)&wqkvT, g_WqkvT);
    cudaGetSymbolAddress((void**)&woutT, g_WoutT);

    cudaFuncSetAttribute(flash_attn_tc,
                         cudaFuncAttributeMaxDynamicSharedMemorySize, FA_SMEM);

    // 0) RoPE table
    rope_table_kernel<<<(T_SEQ * 32 + 255) / 256, 256>>>();

    // 0b) Transpose weights to [N][K]
    transpose_kernel<<<dim3(QKV_COLS / 32, DM / 32), dim3(32, 8)>>>(
        Wqkv, wqkvT, DM, QKV_COLS);
    transpose_kernel<<<dim3(DM / 32, DM / 32), dim3(32, 8)>>>(
        Wout, woutT, DM, DM);

    // 1) QKV projection (tf32 mma.sync)
    gemm_tf32<<<dim3(QKV_COLS / 128, ROWS / 128), 256>>>(
        x, wqkvT, qkv, ROWS, QKV_COLS, DM);

    // 2) RoPE on q,k in-place (table lookup)
    {
        int total = ROWS * NHEAD * (HDIM / 2);
        rope_kernel<<<(total + 255) / 256, 256>>>();
    }

    // 3) Causal flash attention (tf32 tensor cores)
    flash_attn_tc<<<dim3(T_SEQ / 128, NHEAD, B_BATCH), 256, FA_SMEM>>>();

    // 4) Output projection (tf32 mma.sync)
    gemm_tf32<<<dim3(DM / 128, ROWS / 128), 256>>>(
        attn, woutT, out, ROWS, DM, DM);
}

// round 6
// speedup vs baseline: 3.3001x; 1.0428x over previous
#include <cuda_runtime.h>
#include <cstdint>
#include <math.h>

#define T_SEQ    2048
#define B_BATCH  2
#define DM       1024
#define NHEAD    16
#define HDIM     64
#define ROWS     (B_BATCH * T_SEQ)      // 4096
#define QKV_COLS (3 * DM)               // 3072

// Scratch (allocation-guard compliant: device globals)
__device__ float g_qkv[(size_t)ROWS * QKV_COLS];     // ~50 MB (QKV GEMM out)
__device__ float g_attn[(size_t)ROWS * DM];          // ~17 MB (tf32-rounded)
__device__ float g_x32[(size_t)ROWS * DM];           // 16 MB  x pre-rounded
__device__ float g_WqkvT[(size_t)QKV_COLS * DM];     // 12 MB  [N][K] tf32
__device__ float g_WoutT[(size_t)DM * DM];           // 4 MB   [N][K] tf32
__device__ float g_rope_tab[(size_t)T_SEQ * 32 * 2]; // 512 KB (sin,cos)
// Packed per-head tf32 tensors [b][h][t][64]
__device__ float g_qpk[(size_t)ROWS * DM];           // 16 MB (pre-scaled 1/8)
__device__ float g_kpk[(size_t)ROWS * DM];           // 16 MB
__device__ float g_vpk[(size_t)ROWS * DM];           // 16 MB

__device__ __forceinline__ uint32_t f2tf32(float x) {
    uint32_t r;
    asm("cvt.rna.tf32.f32 %0, %1;" : "=r"(r) : "f"(x));
    return r;
}
__device__ __forceinline__ float f2tf32f(float x) {
    return __uint_as_float(f2tf32(x));
}
__device__ __forceinline__ uint32_t smem_u32(const void* p) {
    uint32_t a;
    asm("{ .reg .u64 t; cvta.to.shared.u64 t, %1; cvt.u32.u64 %0, t; }"
        : "=r"(a) : "l"(p));
    return a;
}
__device__ __forceinline__ void cp16(uint32_t dst, const void* src) {
    asm volatile("cp.async.cg.shared.global [%0], [%1], 16;"
                 :: "r"(dst), "l"(src));
}
#define CP_COMMIT() asm volatile("cp.async.commit_group;" ::: "memory")
#define CP_WAIT0()  asm volatile("cp.async.wait_group 0;" ::: "memory")
#define CP_WAIT1()  asm volatile("cp.async.wait_group 1;" ::: "memory")

__device__ __forceinline__ void mma_tf32(
    float* c, uint32_t a0, uint32_t a1, uint32_t a2, uint32_t a3,
    uint32_t b0, uint32_t b1)
{
    asm volatile(
        "mma.sync.aligned.m16n8k8.row.col.f32.tf32.tf32.f32 "
        "{%0,%1,%2,%3}, {%4,%5,%6,%7}, {%8,%9}, {%0,%1,%2,%3};"
        : "+f"(c[0]), "+f"(c[1]), "+f"(c[2]), "+f"(c[3])
        : "r"(a0), "r"(a1), "r"(a2), "r"(a3), "r"(b0), "r"(b1));
}

// ===========================================================================
// Transpose + tf32 round: src [R][C] -> dst [C][R]
// ===========================================================================
__global__ void transpose_kernel(const float* __restrict__ src,
                                 float* __restrict__ dst, int R, int C)
{
    __shared__ float tile[32][33];
    int c0 = blockIdx.x * 32, r0 = blockIdx.y * 32;
    int x = threadIdx.x, y = threadIdx.y;   // 32 x 8
#pragma unroll
    for (int i = 0; i < 32; i += 8)
        tile[y + i][x] = f2tf32f(src[(size_t)(r0 + y + i) * C + c0 + x]);
    __syncthreads();
#pragma unroll
    for (int i = 0; i < 32; i += 8)
        dst[(size_t)(c0 + y + i) * R + r0 + x] = tile[x][y + i];
}

// x -> tf32-rounded copy
__global__ void convert_x_kernel(const float* __restrict__ x)
{
    int i = blockIdx.x * blockDim.x + threadIdx.x;     // 1M threads, float4
    float4 v = *(const float4*)(x + 4 * (size_t)i);
    float4 o = {f2tf32f(v.x), f2tf32f(v.y), f2tf32f(v.z), f2tf32f(v.w)};
    *(float4*)(g_x32 + 4 * (size_t)i) = o;
}

// ===========================================================================
// TF32 mma.sync GEMM with cp.async double buffering.
// Operands MUST be pre-rounded to tf32 bit patterns.
// C[M,N] = A[M,K] @ Bt[N,K]^T. 128x128 block, BK=16, 256 thr, warp 64x32.
// ===========================================================================
#define SST 20   // smem row stride (floats); 80B = 16B-aligned rows

__global__ __launch_bounds__(256) void gemm_tf32(
    const float* __restrict__ A, const float* __restrict__ Bt,
    float* __restrict__ C, int M, int N, int K)
{
    __shared__ uint32_t As[2][128 * SST];
    __shared__ uint32_t Bs[2][128 * SST];

    const int tid  = threadIdx.x;
    const int lane = tid & 31;
    const int wid  = tid >> 5;
    const int wm   = (wid >> 2) * 64;
    const int wn   = (wid & 3) * 32;
    const int bm   = blockIdx.y * 128;
    const int bn   = blockIdx.x * 128;
    const int gid  = lane >> 2;
    const int tig  = lane & 3;

    const uint32_t as0 = smem_u32(&As[0][0]);
    const uint32_t bs0 = smem_u32(&Bs[0][0]);
    const int r0 = tid >> 2, c4 = (tid & 3) * 4;      // chunk of 4 floats

    float acc[4][4][4];
#pragma unroll
    for (int i = 0; i < 4; i++)
#pragma unroll
        for (int j = 0; j < 4; j++)
#pragma unroll
            for (int q = 0; q < 4; q++) acc[i][j][q] = 0.0f;

    const int niter = K >> 4;

    // issue k-chunk `it` into buffer `bf`
    auto issue = [&](int it, int bf) {
        const int k0 = it << 4;
        const uint32_t ao = as0 + (uint32_t)(bf * 128 * SST + r0 * SST + c4) * 4;
        const uint32_t bo = bs0 + (uint32_t)(bf * 128 * SST + r0 * SST + c4) * 4;
        cp16(ao,                 A  + (size_t)(bm + r0)      * K + k0 + c4);
        cp16(ao + 64 * SST * 4,  A  + (size_t)(bm + r0 + 64) * K + k0 + c4);
        cp16(bo,                 Bt + (size_t)(bn + r0)      * K + k0 + c4);
        cp16(bo + 64 * SST * 4,  Bt + (size_t)(bn + r0 + 64) * K + k0 + c4);
    };

    issue(0, 0);
    CP_COMMIT();

    for (int it = 0; it < niter; it++) {
        const int buf = it & 1;
        const bool more = (it + 1) < niter;
        if (more) { issue(it + 1, buf ^ 1); CP_COMMIT(); }
        if (more) { CP_WAIT1(); } else { CP_WAIT0(); }
        __syncthreads();

#pragma unroll
        for (int ks = 0; ks < 16; ks += 8) {
            uint32_t afr[4][4], bfr[4][2];
#pragma unroll
            for (int mt = 0; mt < 4; mt++) {
                const int rb = wm + mt * 16;
                afr[mt][0] = As[buf][(rb + gid)     * SST + ks + tig];
                afr[mt][1] = As[buf][(rb + gid + 8) * SST + ks + tig];
                afr[mt][2] = As[buf][(rb + gid)     * SST + ks + tig + 4];
                afr[mt][3] = As[buf][(rb + gid + 8) * SST + ks + tig + 4];
            }
#pragma unroll
            for (int nt = 0; nt < 4; nt++) {
                const int nb = wn + nt * 8;
                bfr[nt][0] = Bs[buf][(nb + gid) * SST + ks + tig];
                bfr[nt][1] = Bs[buf][(nb + gid) * SST + ks + tig + 4];
            }
#pragma unroll
            for (int mt = 0; mt < 4; mt++)
#pragma unroll
                for (int nt = 0; nt < 4; nt++)
                    mma_tf32(acc[mt][nt], afr[mt][0], afr[mt][1], afr[mt][2],
                             afr[mt][3], bfr[nt][0], bfr[nt][1]);
        }
        __syncthreads();
    }

#pragma unroll
    for (int mt = 0; mt < 4; mt++) {
        const int rb = bm + wm + mt * 16;
#pragma unroll
        for (int nt = 0; nt < 4; nt++) {
            const int cb = bn + wn + nt * 8 + 2 * tig;
            float2 lo = {acc[mt][nt][0], acc[mt][nt][1]};
            float2 hi = {acc[mt][nt][2], acc[mt][nt][3]};
            *(float2*)(C + (size_t)(rb + gid)     * N + cb) = lo;
            *(float2*)(C + (size_t)(rb + gid + 8) * N + cb) = hi;
        }
    }
}

// ===========================================================================
// RoPE table + rope/pack: rotate q,k, scale q by 1/8, tf32-round, and pack
// q,k,v into per-head contiguous [b][h][t][64] layout.
// ===========================================================================
__global__ void rope_table_kernel()
{
    int idx = blockIdx.x * blockDim.x + threadIdx.x;   // 65536
    if (idx >= T_SEQ * 32) return;
    int i = idx & 31;
    int t = idx >> 5;
    double ang = (double)t * pow(10000.0, -(double)i / 32.0);
    g_rope_tab[2 * idx + 0] = (float)sin(ang);
    g_rope_tab[2 * idx + 1] = (float)cos(ang);
}

__global__ void rope_pack_kernel()
{
    int idx = blockIdx.x * blockDim.x + threadIdx.x;
    const int total = ROWS * NHEAD * (HDIM / 2);
    if (idx >= total) return;
    int i = idx & 31;          // pair index
    int h = (idx >> 5) & 15;   // head
    int r = idx >> 9;          // row 0..4095
    int t = r & (T_SEQ - 1);
    int b = r >> 11;

    float sn = g_rope_tab[2 * (t * 32 + i) + 0];
    float cs = g_rope_tab[2 * (t * 32 + i) + 1];

    const float* src = g_qkv + (size_t)r * QKV_COLS + h * HDIM + 2 * i;
    const size_t po = ((size_t)(b * NHEAD + h) * T_SEQ + t) * HDIM + 2 * i;

    {   // q: rotate, scale 1/8
        float x0 = src[0], x1 = src[1];
        g_qpk[po + 0] = f2tf32f((x0 * cs - x1 * sn) * 0.125f);
        g_qpk[po + 1] = f2tf32f((x1 * cs + x0 * sn) * 0.125f);
    }
    {   // k: rotate
        float x0 = src[DM], x1 = src[DM + 1];
        g_kpk[po + 0] = f2tf32f(x0 * cs - x1 * sn);
        g_kpk[po + 1] = f2tf32f(x1 * cs + x0 * sn);
    }
    {   // v: copy
        g_vpk[po + 0] = f2tf32f(src[2 * DM]);
        g_vpk[po + 1] = f2tf32f(src[2 * DM + 1]);
    }
}

// ===========================================================================
// Tensor-core causal flash attention, cp.async double-buffered K/V.
// Grid (16 qtiles, 16 heads, 2 batch), 256 threads = 8 warps.
// Warp w owns q-rows [16w, 16w+16). KV tiles of 64 keys. smem stride 72.
// ===========================================================================
#define SAT 72
#define FA_SMEM ((2 * 64 * SAT + 2 * 64 * SAT + 128 * SAT) * 4)

__global__ __launch_bounds__(256) void flash_attn_tc()
{
    extern __shared__ uint32_t smu[];
    uint32_t* Ksm = smu;                       // [2][key][d]  2 x 64 x 72
    uint32_t* Vsm = Ksm + 2 * 64 * SAT;        // [2][key][d]
    uint32_t* Psm = Vsm + 2 * 64 * SAT;        // [m][key]    128 x 72

    const int tid  = threadIdx.x;
    const int lane = tid & 31;
    const int wid  = tid >> 5;
    const int gid  = lane >> 2;
    const int tig  = lane & 3;
    const int qi = (int)(gridDim.x - 1 - blockIdx.x);
    const int h = blockIdx.y, b = blockIdx.z;
    const int qbase = qi * 128;
    const int bh = b * NHEAD + h;
    const int wrow = 16 * wid;

    const uint32_t ksm0 = smem_u32(Ksm);
    const uint32_t vsm0 = smem_u32(Vsm);
    const float* kbase_p = g_kpk + (size_t)bh * T_SEQ * HDIM;
    const float* vbase_p = g_vpk + (size_t)bh * T_SEQ * HDIM;

    // issue cp.async for KV tile kt into stage st
    auto issue_kv = [&](int kt, int st) {
        const int n = tid >> 2;                 // key 0..63
        const int c = (tid & 3) * 16;           // float offset (4 chunks of 4)
        const size_t go = (size_t)(kt * 64 + n) * HDIM + c;
        const uint32_t so = (uint32_t)(st * 64 * SAT + n * SAT + c) * 4;
#pragma unroll
        for (int j = 0; j < 4; j++) {
            cp16(ksm0 + so + j * 16, kbase_p + go + j * 4);
            cp16(vsm0 + so + j * 16, vbase_p + go + j * 4);
        }
    };

    // ---- stage Q into Psm (already tf32 + scaled) ----
    {
        int m = tid >> 1;
        int d0 = (tid & 1) * 32;
        const float* src = g_qpk + ((size_t)bh * T_SEQ + qbase + m) * HDIM + d0;
#pragma unroll
        for (int j = 0; j < 8; j++) {
            uint4 v = *(const uint4*)(src + 4 * j);
            *(uint4*)&Psm[m * SAT + d0 + 4 * j] = v;
        }
    }

    const int nkt = qbase / 64 + 2;
    issue_kv(0, 0);
    CP_COMMIT();
    __syncthreads();   // Q staged

    // ---- hoist Q fragments ----
    uint32_t qf[8][4];
#pragma unroll
    for (int ks = 0; ks < 8; ks++) {
        qf[ks][0] = Psm[(wrow + gid)     * SAT + ks * 8 + tig];
        qf[ks][1] = Psm[(wrow + gid + 8) * SAT + ks * 8 + tig];
        qf[ks][2] = Psm[(wrow + gid)     * SAT + ks * 8 + tig + 4];
        qf[ks][3] = Psm[(wrow + gid + 8) * SAT + ks * 8 + tig + 4];
    }

    float Oacc[8][4];
#pragma unroll
    for (int nt = 0; nt < 8; nt++)
#pragma unroll
        for (int q = 0; q < 4; q++) Oacc[nt][q] = 0.0f;
    float mrow0 = -1e30f, mrow1 = -1e30f, lrow0 = 0.0f, lrow1 = 0.0f;

    for (int kt = 0; kt < nkt; kt++) {
        const int st = kt & 1;
        const int kb = kt * 64;
        const bool more = (kt + 1) < nkt;
        if (more) { issue_kv(kt + 1, st ^ 1); CP_COMMIT(); }
        if (more) { CP_WAIT1(); } else { CP_WAIT0(); }
        __syncthreads();

        const uint32_t* Kst = Ksm + st * 64 * SAT;
        const uint32_t* Vst = Vsm + st * 64 * SAT;

        // ---- S = Q @ K^T ----
        float sacc[8][4];
#pragma unroll
        for (int nt = 0; nt < 8; nt++)
#pragma unroll
            for (int q = 0; q < 4; q++) sacc[nt][q] = 0.0f;

#pragma unroll
        for (int ks = 0; ks < 8; ks++) {
#pragma unroll
            for (int nt = 0; nt < 8; nt++) {
                uint32_t b0 = Kst[(nt * 8 + gid) * SAT + ks * 8 + tig];
                uint32_t b1 = Kst[(nt * 8 + gid) * SAT + ks * 8 + tig + 4];
                mma_tf32(sacc[nt], qf[ks][0], qf[ks][1], qf[ks][2], qf[ks][3],
                         b0, b1);
            }
        }

        // ---- causal mask ----
        const int r0g = qbase + wrow + gid;
        if (kb + 63 > qbase) {
#pragma unroll
            for (int nt = 0; nt < 8; nt++) {
                int col = kb + nt * 8 + 2 * tig;
                if (col     > r0g)     sacc[nt][0] = -1e30f;
                if (col + 1 > r0g)     sacc[nt][1] = -1e30f;
                if (col     > r0g + 8) sacc[nt][2] = -1e30f;
                if (col + 1 > r0g + 8) sacc[nt][3] = -1e30f;
            }
        }

        // ---- online softmax ----
        float mx0 = -1e30f, mx1 = -1e30f;
#pragma unroll
        for (int nt = 0; nt < 8; nt++) {
            mx0 = fmaxf(mx0, fmaxf(sacc[nt][0], sacc[nt][1]));
            mx1 = fmaxf(mx1, fmaxf(sacc[nt][2], sacc[nt][3]));
        }
        mx0 = fmaxf(mx0, __shfl_xor_sync(0xffffffffu, mx0, 1));
        mx0 = fmaxf(mx0, __shfl_xor_sync(0xffffffffu, mx0, 2));
        mx1 = fmaxf(mx1, __shfl_xor_sync(0xffffffffu, mx1, 1));
        mx1 = fmaxf(mx1, __shfl_xor_sync(0xffffffffu, mx1, 2));
        const float nm0 = fmaxf(mrow0, mx0);
        const float nm1 = fmaxf(mrow1, mx1);

        float sum0 = 0.0f, sum1 = 0.0f;
#pragma unroll
        for (int nt = 0; nt < 8; nt++) {
            float p00 = __expf(sacc[nt][0] - nm0);
            float p01 = __expf(sacc[nt][1] - nm0);
            float p10 = __expf(sacc[nt][2] - nm1);
            float p11 = __expf(sacc[nt][3] - nm1);
            sum0 += p00 + p01;
            sum1 += p10 + p11;
            uint2 u0 = {f2tf32(p00), f2tf32(p01)};
            uint2 u1 = {f2tf32(p10), f2tf32(p11)};
            *(uint2*)&Psm[(wrow + gid)     * SAT + nt * 8 + 2 * tig] = u0;
            *(uint2*)&Psm[(wrow + gid + 8) * SAT + nt * 8 + 2 * tig] = u1;
        }
        sum0 += __shfl_xor_sync(0xffffffffu, sum0, 1);
        sum0 += __shfl_xor_sync(0xffffffffu, sum0, 2);
        sum1 += __shfl_xor_sync(0xffffffffu, sum1, 1);
        sum1 += __shfl_xor_sync(0xffffffffu, sum1, 2);

        const float a0 = __expf(mrow0 - nm0);
        const float a1 = __expf(mrow1 - nm1);
        lrow0 = lrow0 * a0 + sum0;
        lrow1 = lrow1 * a1 + sum1;
        mrow0 = nm0; mrow1 = nm1;
#pragma unroll
        for (int nt = 0; nt < 8; nt++) {
            Oacc[nt][0] *= a0; Oacc[nt][1] *= a0;
            Oacc[nt][2] *= a1; Oacc[nt][3] *= a1;
        }
        __syncwarp();

        // ---- O += P @ V ----
#pragma unroll
        for (int ks = 0; ks < 8; ks++) {
            uint32_t a0f = Psm[(wrow + gid)     * SAT + ks * 8 + tig];
            uint32_t a1f = Psm[(wrow + gid + 8) * SAT + ks * 8 + tig];
            uint32_t a2f = Psm[(wrow + gid)     * SAT + ks * 8 + tig + 4];
            uint32_t a3f = Psm[(wrow + gid + 8) * SAT + ks * 8 + tig + 4];
#pragma unroll
            for (int nt = 0; nt < 8; nt++) {
                uint32_t b0 = Vst[(ks * 8 + tig)     * SAT + nt * 8 + gid];
                uint32_t b1 = Vst[(ks * 8 + tig + 4) * SAT + nt * 8 + gid];
                mma_tf32(Oacc[nt], a0f, a1f, a2f, a3f, b0, b1);
            }
        }
        __syncthreads();   // stage st free for reuse at kt+2
    }

    // ---- normalize + store (tf32-rounded so out-proj needs no conversion) ----
    const float i0 = 1.0f / lrow0;
    const float i1 = 1.0f / lrow1;
    const int r0g = qbase + wrow + gid;
#pragma unroll
    for (int nt = 0; nt < 8; nt++) {
        const int c = h * HDIM + nt * 8 + 2 * tig;
        float2 lo = {f2tf32f(Oacc[nt][0] * i0), f2tf32f(Oacc[nt][1] * i0)};
        float2 hi = {f2tf32f(Oacc[nt][2] * i1), f2tf32f(Oacc[nt][3] * i1)};
        *(float2*)&g_attn[((size_t)b * T_SEQ + r0g)     * DM + c] = lo;
        *(float2*)&g_attn[((size_t)b * T_SEQ + r0g + 8) * DM + c] = hi;
    }
}

// ===========================================================================
extern "C" void kernel_launch(void* const* d_in, const int* in_sizes, int n_in,
                              void* d_out, int out_size)
{
    const float* x    = (const float*)d_in[0];
    const float* Wqkv = (const float*)d_in[1];
    const float* Wout = (const float*)d_in[2];
    float* out = (float*)d_out;

    float *qkv = nullptr, *attn = nullptr, *wqkvT = nullptr, *woutT = nullptr;
    float *x32 = nullptr;
    cudaGetSymbolAddress((void**)&qkv,   g_qkv);
    cudaGetSymbolAddress((void**)&attn,  g_attn);
    cudaGetSymbolAddress((void**)&wqkvT, g_WqkvT);
    cudaGetSymbolAddress((void**)&woutT, g_WoutT);
    cudaGetSymbolAddress((void**)&x32,   g_x32);

    cudaFuncSetAttribute(flash_attn_tc,
                         cudaFuncAttributeMaxDynamicSharedMemorySize, FA_SMEM);

    // 0) RoPE table, weight transposes (+tf32 round), x round
    rope_table_kernel<<<(T_SEQ * 32 + 255) / 256, 256>>>();
    transpose_kernel<<<dim3(QKV_COLS / 32, DM / 32), dim3(32, 8)>>>(
        Wqkv, wqkvT, DM, QKV_COLS);
    transpose_kernel<<<dim3(DM / 32, DM / 32), dim3(32, 8)>>>(
        Wout, woutT, DM, DM);
    convert_x_kernel<<<(ROWS * DM / 4) / 256, 256>>>(x);

    // 1) QKV projection
    gemm_tf32<<<dim3(QKV_COLS / 128, ROWS / 128), 256>>>(
        x32, wqkvT, qkv, ROWS, QKV_COLS, DM);

    // 2) RoPE + pack q,k,v per-head (tf32)
    {
        int total = ROWS * NHEAD * (HDIM / 2);
        rope_pack_kernel<<<(total + 255) / 256, 256>>>();
    }

    // 3) Causal flash attention (tf32 tensor cores, cp.async pipeline)
    flash_attn_tc<<<dim3(T_SEQ / 128, NHEAD, B_BATCH), 256, FA_SMEM>>>();

    // 4) Output projection
    gemm_tf32<<<dim3(DM / 128, ROWS / 128), 256>>>(
        attn, woutT, out, ROWS, DM, DM);
}

// round 7
// speedup vs baseline: 3.3768x; 1.0232x over previous
#include <cuda_runtime.h>
#include <cstdint>
#include <math.h>

#define T_SEQ    2048
#define B_BATCH  2
#define DM       1024
#define NHEAD    16
#define HDIM     64
#define ROWS     (B_BATCH * T_SEQ)      // 4096
#define QKV_COLS (3 * DM)               // 3072

// Scratch (allocation-guard compliant: device globals)
__device__ float g_attn[(size_t)ROWS * DM];          // 16 MB (tf32-rounded)
__device__ float g_x32[(size_t)ROWS * DM];           // 16 MB  x pre-rounded
__device__ float g_WqkvT[(size_t)QKV_COLS * DM];     // 12 MB  [N][K] tf32
__device__ float g_WoutT[(size_t)DM * DM];           // 4 MB   [N][K] tf32
__device__ float g_rope_tab[(size_t)T_SEQ * 32 * 2]; // 512 KB (sin,cos)
// Packed per-head tf32 tensors [b][h][t][64]
__device__ float g_qpk[(size_t)ROWS * DM];           // 16 MB (pre-scaled 1/8)
__device__ float g_kpk[(size_t)ROWS * DM];           // 16 MB
__device__ float g_vpk[(size_t)ROWS * DM];           // 16 MB

__device__ __forceinline__ uint32_t f2tf32(float x) {
    uint32_t r;
    asm("cvt.rna.tf32.f32 %0, %1;" : "=r"(r) : "f"(x));
    return r;
}
__device__ __forceinline__ float f2tf32f(float x) {
    return __uint_as_float(f2tf32(x));
}
__device__ __forceinline__ uint32_t smem_u32(const void* p) {
    uint32_t a;
    asm("{ .reg .u64 t; cvta.to.shared.u64 t, %1; cvt.u32.u64 %0, t; }"
        : "=r"(a) : "l"(p));
    return a;
}
__device__ __forceinline__ void cp16(uint32_t dst, const void* src) {
    asm volatile("cp.async.cg.shared.global [%0], [%1], 16;"
                 :: "r"(dst), "l"(src));
}
#define CP_COMMIT() asm volatile("cp.async.commit_group;" ::: "memory")
#define CP_WAIT2()  asm volatile("cp.async.wait_group 2;" ::: "memory")
#define CP_WAIT1()  asm volatile("cp.async.wait_group 1;" ::: "memory")
#define CP_WAIT0()  asm volatile("cp.async.wait_group 0;" ::: "memory")

__device__ __forceinline__ void mma_tf32(
    float* c, uint32_t a0, uint32_t a1, uint32_t a2, uint32_t a3,
    uint32_t b0, uint32_t b1)
{
    asm volatile(
        "mma.sync.aligned.m16n8k8.row.col.f32.tf32.tf32.f32 "
        "{%0,%1,%2,%3}, {%4,%5,%6,%7}, {%8,%9}, {%0,%1,%2,%3};"
        : "+f"(c[0]), "+f"(c[1]), "+f"(c[2]), "+f"(c[3])
        : "r"(a0), "r"(a1), "r"(a2), "r"(a3), "r"(b0), "r"(b1));
}

// ===========================================================================
// Transpose + tf32 round: src [R][C] -> dst [C][R]
// ===========================================================================
__global__ void transpose_kernel(const float* __restrict__ src,
                                 float* __restrict__ dst, int R, int C)
{
    __shared__ float tile[32][33];
    int c0 = blockIdx.x * 32, r0 = blockIdx.y * 32;
    int x = threadIdx.x, y = threadIdx.y;   // 32 x 8
#pragma unroll
    for (int i = 0; i < 32; i += 8)
        tile[y + i][x] = f2tf32f(src[(size_t)(r0 + y + i) * C + c0 + x]);
    __syncthreads();
#pragma unroll
    for (int i = 0; i < 32; i += 8)
        dst[(size_t)(c0 + y + i) * R + r0 + x] = tile[x][y + i];
}

// x -> tf32-rounded copy
__global__ void convert_x_kernel(const float* __restrict__ x)
{
    int i = blockIdx.x * blockDim.x + threadIdx.x;
    float4 v = *(const float4*)(x + 4 * (size_t)i);
    float4 o = {f2tf32f(v.x), f2tf32f(v.y), f2tf32f(v.z), f2tf32f(v.w)};
    *(float4*)(g_x32 + 4 * (size_t)i) = o;
}

// ===========================================================================
// RoPE table
// ===========================================================================
__global__ void rope_table_kernel()
{
    int idx = blockIdx.x * blockDim.x + threadIdx.x;   // 65536
    if (idx >= T_SEQ * 32) return;
    int i = idx & 31;
    int t = idx >> 5;
    double ang = (double)t * pow(10000.0, -(double)i / 32.0);
    g_rope_tab[2 * idx + 0] = (float)sin(ang);
    g_rope_tab[2 * idx + 1] = (float)cos(ang);
}

// ===========================================================================
// Shared tf32 GEMM mainloop: 128x128 block, BK=16, 4-stage cp.async,
// ONE __syncthreads per chunk. Operands pre-rounded tf32.
// ===========================================================================
#define SST 20
#define NSTG 4
#define STG_FLOATS (128 * SST)
#define GEMM_SMEM (NSTG * 2 * STG_FLOATS * 4)   // 81920 B

__device__ __forceinline__ void gemm_mainloop(
    const float* __restrict__ A, const float* __restrict__ Bt,
    int K, int bm, int bn, float acc[4][4][4], uint32_t* sm)
{
    const int tid  = threadIdx.x;
    const int lane = tid & 31;
    const int wid  = tid >> 5;
    const int wm   = (wid >> 2) * 64;
    const int wn   = (wid & 3) * 32;
    const int gid  = lane >> 2;
    const int tig  = lane & 3;

    uint32_t* As = sm;
    uint32_t* Bs = sm + NSTG * STG_FLOATS;
    const uint32_t as0 = smem_u32(As);
    const uint32_t bs0 = smem_u32(Bs);
    const int r0 = tid >> 2, c4 = (tid & 3) * 4;

    auto issue = [&](int ch) {
        const int s  = ch & (NSTG - 1);
        const int k0 = ch << 4;
        const uint32_t ao = as0 + (uint32_t)(s * STG_FLOATS + r0 * SST + c4) * 4;
        const uint32_t bo = bs0 + (uint32_t)(s * STG_FLOATS + r0 * SST + c4) * 4;
        cp16(ao,                A  + (size_t)(bm + r0)      * K + k0 + c4);
        cp16(ao + 64 * SST * 4, A  + (size_t)(bm + r0 + 64) * K + k0 + c4);
        cp16(bo,                Bt + (size_t)(bn + r0)      * K + k0 + c4);
        cp16(bo + 64 * SST * 4, Bt + (size_t)(bn + r0 + 64) * K + k0 + c4);
        CP_COMMIT();
    };

    const int niter = K >> 4;    // 64
    issue(0); issue(1); issue(2);

    for (int it = 0; it < niter; it++) {
        CP_WAIT2();
        __syncthreads();
        if (it + 3 < niter) issue(it + 3);   // stage (it-1)&3: freed by the sync

        const uint32_t* Ab = As + (it & (NSTG - 1)) * STG_FLOATS;
        const uint32_t* Bb = Bs + (it & (NSTG - 1)) * STG_FLOATS;

#pragma unroll
        for (int ks = 0; ks < 16; ks += 8) {
            uint32_t afr[4][4], bfr[4][2];
#pragma unroll
            for (int mt = 0; mt < 4; mt++) {
                const int rb = wm + mt * 16;
                afr[mt][0] = Ab[(rb + gid)     * SST + ks + tig];
                afr[mt][1] = Ab[(rb + gid + 8) * SST + ks + tig];
                afr[mt][2] = Ab[(rb + gid)     * SST + ks + tig + 4];
                afr[mt][3] = Ab[(rb + gid + 8) * SST + ks + tig + 4];
            }
#pragma unroll
            for (int nt = 0; nt < 4; nt++) {
                const int nb = wn + nt * 8;
                bfr[nt][0] = Bb[(nb + gid) * SST + ks + tig];
                bfr[nt][1] = Bb[(nb + gid) * SST + ks + tig + 4];
            }
#pragma unroll
            for (int mt = 0; mt < 4; mt++)
#pragma unroll
                for (int nt = 0; nt < 4; nt++)
                    mma_tf32(acc[mt][nt], afr[mt][0], afr[mt][1], afr[mt][2],
                             afr[mt][3], bfr[nt][0], bfr[nt][1]);
        }
    }
}

// ---------------------------------------------------------------------------
// QKV GEMM with fused RoPE + per-head pack epilogue.
// Column c: region c/1024 (0=q,1=k,2=v), head (c%1024)/64, d = c%64.
// acc pair [0],[1] = columns (2i, 2i+1) of one row: a native rotation pair.
// ---------------------------------------------------------------------------
__global__ __launch_bounds__(256, 2) void gemm_qkv_fused(
    const float* __restrict__ A, const float* __restrict__ Bt, int K)
{
    extern __shared__ uint32_t sm[];
    const int tid  = threadIdx.x;
    const int lane = tid & 31;
    const int wid  = tid >> 5;
    const int wm   = (wid >> 2) * 64;
    const int wn   = (wid & 3) * 32;
    const int bm   = blockIdx.y * 128;
    const int bn   = blockIdx.x * 128;
    const int gid  = lane >> 2;
    const int tig  = lane & 3;

    float acc[4][4][4];
#pragma unroll
    for (int i = 0; i < 4; i++)
#pragma unroll
        for (int j = 0; j < 4; j++)
#pragma unroll
            for (int q = 0; q < 4; q++) acc[i][j][q] = 0.0f;

    gemm_mainloop(A, Bt, K, bm, bn, acc, sm);

#pragma unroll
    for (int mt = 0; mt < 4; mt++) {
        const int rb = bm + wm + mt * 16 + gid;
#pragma unroll
        for (int nt = 0; nt < 4; nt++) {
            const int c  = bn + wn + nt * 8 + 2 * tig;
            const int region = c >> 10;
            const int cc = c & 1023;
            const int h  = cc >> 6;
            const int d  = cc & 63;
            const int i2 = d >> 1;
#pragma unroll
            for (int half = 0; half < 2; half++) {
                const int r = rb + half * 8;
                const int t = r & (T_SEQ - 1);
                const int b = r >> 11;
                const float a0 = acc[mt][nt][2 * half + 0];
                const float a1 = acc[mt][nt][2 * half + 1];
                const size_t dst =
                    ((size_t)(b * NHEAD + h) * T_SEQ + t) * HDIM + d;
                if (region == 2) {
                    float2 o = {f2tf32f(a0), f2tf32f(a1)};
                    *(float2*)&g_vpk[dst] = o;
                } else {
                    const float sn = g_rope_tab[2 * (t * 32 + i2) + 0];
                    const float cs = g_rope_tab[2 * (t * 32 + i2) + 1];
                    float o0 = a0 * cs - a1 * sn;
                    float o1 = a1 * cs + a0 * sn;
                    if (region == 0) {
                        float2 o = {f2tf32f(o0 * 0.125f), f2tf32f(o1 * 0.125f)};
                        *(float2*)&g_qpk[dst] = o;
                    } else {
                        float2 o = {f2tf32f(o0), f2tf32f(o1)};
                        *(float2*)&g_kpk[dst] = o;
                    }
                }
            }
        }
    }
}

// ---------------------------------------------------------------------------
// Plain tf32 GEMM (output projection)
// ---------------------------------------------------------------------------
__global__ __launch_bounds__(256, 2) void gemm_tf32(
    const float* __restrict__ A, const float* __restrict__ Bt,
    float* __restrict__ C, int N, int K)
{
    extern __shared__ uint32_t sm[];
    const int tid  = threadIdx.x;
    const int lane = tid & 31;
    const int wid  = tid >> 5;
    const int wm   = (wid >> 2) * 64;
    const int wn   = (wid & 3) * 32;
    const int bm   = blockIdx.y * 128;
    const int bn   = blockIdx.x * 128;
    const int gid  = lane >> 2;
    const int tig  = lane & 3;

    float acc[4][4][4];
#pragma unroll
    for (int i = 0; i < 4; i++)
#pragma unroll
        for (int j = 0; j < 4; j++)
#pragma unroll
            for (int q = 0; q < 4; q++) acc[i][j][q] = 0.0f;

    gemm_mainloop(A, Bt, K, bm, bn, acc, sm);

#pragma unroll
    for (int mt = 0; mt < 4; mt++) {
        const int rb = bm + wm + mt * 16;
#pragma unroll
        for (int nt = 0; nt < 4; nt++) {
            const int cb = bn + wn + nt * 8 + 2 * tig;
            float2 lo = {acc[mt][nt][0], acc[mt][nt][1]};
            float2 hi = {acc[mt][nt][2], acc[mt][nt][3]};
            *(float2*)(C + (size_t)(rb + gid)     * N + cb) = lo;
            *(float2*)(C + (size_t)(rb + gid + 8) * N + cb) = hi;
        }
    }
}

// ===========================================================================
// Tensor-core causal flash attention (R6-proven, unchanged)
// ===========================================================================
#define SAT 72
#define FA_SMEM ((2 * 64 * SAT + 2 * 64 * SAT + 128 * SAT) * 4)

__global__ __launch_bounds__(256) void flash_attn_tc()
{
    extern __shared__ uint32_t smu[];
    uint32_t* Ksm = smu;
    uint32_t* Vsm = Ksm + 2 * 64 * SAT;
    uint32_t* Psm = Vsm + 2 * 64 * SAT;

    const int tid  = threadIdx.x;
    const int lane = tid & 31;
    const int wid  = tid >> 5;
    const int gid  = lane >> 2;
    const int tig  = lane & 3;
    const int qi = (int)(gridDim.x - 1 - blockIdx.x);
    const int h = blockIdx.y, b = blockIdx.z;
    const int qbase = qi * 128;
    const int bh = b * NHEAD + h;
    const int wrow = 16 * wid;

    const uint32_t ksm0 = smem_u32(Ksm);
    const uint32_t vsm0 = smem_u32(Vsm);
    const float* kbase_p = g_kpk + (size_t)bh * T_SEQ * HDIM;
    const float* vbase_p = g_vpk + (size_t)bh * T_SEQ * HDIM;

    auto issue_kv = [&](int kt, int st) {
        const int n = tid >> 2;
        const int c = (tid & 3) * 16;
        const size_t go = (size_t)(kt * 64 + n) * HDIM + c;
        const uint32_t so = (uint32_t)(st * 64 * SAT + n * SAT + c) * 4;
#pragma unroll
        for (int j = 0; j < 4; j++) {
            cp16(ksm0 + so + j * 16, kbase_p + go + j * 4);
            cp16(vsm0 + so + j * 16, vbase_p + go + j * 4);
        }
    };

    {
        int m = tid >> 1;
        int d0 = (tid & 1) * 32;
        const float* src = g_qpk + ((size_t)bh * T_SEQ + qbase + m) * HDIM + d0;
#pragma unroll
        for (int j = 0; j < 8; j++) {
            uint4 v = *(const uint4*)(src + 4 * j);
            *(uint4*)&Psm[m * SAT + d0 + 4 * j] = v;
        }
    }

    const int nkt = qbase / 64 + 2;
    issue_kv(0, 0);
    CP_COMMIT();
    __syncthreads();

    uint32_t qf[8][4];
#pragma unroll
    for (int ks = 0; ks < 8; ks++) {
        qf[ks][0] = Psm[(wrow + gid)     * SAT + ks * 8 + tig];
        qf[ks][1] = Psm[(wrow + gid + 8) * SAT + ks * 8 + tig];
        qf[ks][2] = Psm[(wrow + gid)     * SAT + ks * 8 + tig + 4];
        qf[ks][3] = Psm[(wrow + gid + 8) * SAT + ks * 8 + tig + 4];
    }

    float Oacc[8][4];
#pragma unroll
    for (int nt = 0; nt < 8; nt++)
#pragma unroll
        for (int q = 0; q < 4; q++) Oacc[nt][q] = 0.0f;
    float mrow0 = -1e30f, mrow1 = -1e30f, lrow0 = 0.0f, lrow1 = 0.0f;

    for (int kt = 0; kt < nkt; kt++) {
        const int st = kt & 1;
        const int kb = kt * 64;
        const bool more = (kt + 1) < nkt;
        if (more) { issue_kv(kt + 1, st ^ 1); CP_COMMIT(); }
        if (more) { CP_WAIT1(); } else { CP_WAIT0(); }
        __syncthreads();

        const uint32_t* Kst = Ksm + st * 64 * SAT;
        const uint32_t* Vst = Vsm + st * 64 * SAT;

        float sacc[8][4];
#pragma unroll
        for (int nt = 0; nt < 8; nt++)
#pragma unroll
            for (int q = 0; q < 4; q++) sacc[nt][q] = 0.0f;

#pragma unroll
        for (int ks = 0; ks < 8; ks++) {
#pragma unroll
            for (int nt = 0; nt < 8; nt++) {
                uint32_t b0 = Kst[(nt * 8 + gid) * SAT + ks * 8 + tig];
                uint32_t b1 = Kst[(nt * 8 + gid) * SAT + ks * 8 + tig + 4];
                mma_tf32(sacc[nt], qf[ks][0], qf[ks][1], qf[ks][2], qf[ks][3],
                         b0, b1);
            }
        }

        const int r0g = qbase + wrow + gid;
        if (kb + 63 > qbase) {
#pragma unroll
            for (int nt = 0; nt < 8; nt++) {
                int col = kb + nt * 8 + 2 * tig;
                if (col     > r0g)     sacc[nt][0] = -1e30f;
                if (col + 1 > r0g)     sacc[nt][1] = -1e30f;
                if (col     > r0g + 8) sacc[nt][2] = -1e30f;
                if (col + 1 > r0g + 8) sacc[nt][3] = -1e30f;
            }
        }

        float mx0 = -1e30f, mx1 = -1e30f;
#pragma unroll
        for (int nt = 0; nt < 8; nt++) {
            mx0 = fmaxf(mx0, fmaxf(sacc[nt][0], sacc[nt][1]));
            mx1 = fmaxf(mx1, fmaxf(sacc[nt][2], sacc[nt][3]));
        }
        mx0 = fmaxf(mx0, __shfl_xor_sync(0xffffffffu, mx0, 1));
        mx0 = fmaxf(mx0, __shfl_xor_sync(0xffffffffu, mx0, 2));
        mx1 = fmaxf(mx1, __shfl_xor_sync(0xffffffffu, mx1, 1));
        mx1 = fmaxf(mx1, __shfl_xor_sync(0xffffffffu, mx1, 2));
        const float nm0 = fmaxf(mrow0, mx0);
        const float nm1 = fmaxf(mrow1, mx1);

        float sum0 = 0.0f, sum1 = 0.0f;
#pragma unroll
        for (int nt = 0; nt < 8; nt++) {
            float p00 = __expf(sacc[nt][0] - nm0);
            float p01 = __expf(sacc[nt][1] - nm0);
            float p10 = __expf(sacc[nt][2] - nm1);
            float p11 = __expf(sacc[nt][3] - nm1);
            sum0 += p00 + p01;
            sum1 += p10 + p11;
            uint2 u0 = {f2tf32(p00), f2tf32(p01)};
            uint2 u1 = {f2tf32(p10), f2tf32(p11)};
            *(uint2*)&Psm[(wrow + gid)     * SAT + nt * 8 + 2 * tig] = u0;
            *(uint2*)&Psm[(wrow + gid + 8) * SAT + nt * 8 + 2 * tig] = u1;
        }
        sum0 += __shfl_xor_sync(0xffffffffu, sum0, 1);
        sum0 += __shfl_xor_sync(0xffffffffu, sum0, 2);
        sum1 += __shfl_xor_sync(0xffffffffu, sum1, 1);
        sum1 += __shfl_xor_sync(0xffffffffu, sum1, 2);

        const float a0 = __expf(mrow0 - nm0);
        const float a1 = __expf(mrow1 - nm1);
        lrow0 = lrow0 * a0 + sum0;
        lrow1 = lrow1 * a1 + sum1;
        mrow0 = nm0; mrow1 = nm1;
#pragma unroll
        for (int nt = 0; nt < 8; nt++) {
            Oacc[nt][0] *= a0; Oacc[nt][1] *= a0;
            Oacc[nt][2] *= a1; Oacc[nt][3] *= a1;
        }
        __syncwarp();

#pragma unroll
        for (int ks = 0; ks < 8; ks++) {
            uint32_t a0f = Psm[(wrow + gid)     * SAT + ks * 8 + tig];
            uint32_t a1f = Psm[(wrow + gid + 8) * SAT + ks * 8 + tig];
            uint32_t a2f = Psm[(wrow + gid)     * SAT + ks * 8 + tig + 4];
            uint32_t a3f = Psm[(wrow + gid + 8) * SAT + ks * 8 + tig + 4];
#pragma unroll
            for (int nt = 0; nt < 8; nt++) {
                uint32_t b0 = Vst[(ks * 8 + tig)     * SAT + nt * 8 + gid];
                uint32_t b1 = Vst[(ks * 8 + tig + 4) * SAT + nt * 8 + gid];
                mma_tf32(Oacc[nt], a0f, a1f, a2f, a3f, b0, b1);
            }
        }
        __syncthreads();
    }

    const float i0 = 1.0f / lrow0;
    const float i1 = 1.0f / lrow1;
    const int r0g = qbase + wrow + gid;
#pragma unroll
    for (int nt = 0; nt < 8; nt++) {
        const int c = h * HDIM + nt * 8 + 2 * tig;
        float2 lo = {f2tf32f(Oacc[nt][0] * i0), f2tf32f(Oacc[nt][1] * i0)};
        float2 hi = {f2tf32f(Oacc[nt][2] * i1), f2tf32f(Oacc[nt][3] * i1)};
        *(float2*)&g_attn[((size_t)b * T_SEQ + r0g)     * DM + c] = lo;
        *(float2*)&g_attn[((size_t)b * T_SEQ + r0g + 8) * DM + c] = hi;
    }
}

// ===========================================================================
extern "C" void kernel_launch(void* const* d_in, const int* in_sizes, int n_in,
                              void* d_out, int out_size)
{
    const float* x    = (const float*)d_in[0];
    const float* Wqkv = (const float*)d_in[1];
    const float* Wout = (const float*)d_in[2];
    float* out = (float*)d_out;

    float *attn = nullptr, *wqkvT = nullptr, *woutT = nullptr, *x32 = nullptr;
    cudaGetSymbolAddress((void**)&attn,  g_attn);
    cudaGetSymbolAddress((void**)&wqkvT, g_WqkvT);
    cudaGetSymbolAddress((void**)&woutT, g_WoutT);
    cudaGetSymbolAddress((void**)&x32,   g_x32);

    cudaFuncSetAttribute(gemm_qkv_fused,
                         cudaFuncAttributeMaxDynamicSharedMemorySize, GEMM_SMEM);
    cudaFuncSetAttribute(gemm_tf32,
                         cudaFuncAttributeMaxDynamicSharedMemorySize, GEMM_SMEM);
    cudaFuncSetAttribute(flash_attn_tc,
                         cudaFuncAttributeMaxDynamicSharedMemorySize, FA_SMEM);

    // 0) RoPE table, weight transposes (+tf32 round), x round
    rope_table_kernel<<<(T_SEQ * 32 + 255) / 256, 256>>>();
    transpose_kernel<<<dim3(QKV_COLS / 32, DM / 32), dim3(32, 8)>>>(
        Wqkv, wqkvT, DM, QKV_COLS);
    transpose_kernel<<<dim3(DM / 32, DM / 32), dim3(32, 8)>>>(
        Wout, woutT, DM, DM);
    convert_x_kernel<<<(ROWS * DM / 4) / 256, 256>>>(x);

    // 1) QKV projection + fused RoPE + per-head pack
    gemm_qkv_fused<<<dim3(QKV_COLS / 128, ROWS / 128), 256, GEMM_SMEM>>>(
        x32, wqkvT, DM);

    // 2) Causal flash attention (tf32 tensor cores, cp.async pipeline)
    flash_attn_tc<<<dim3(T_SEQ / 128, NHEAD, B_BATCH), 256, FA_SMEM>>>();

    // 3) Output projection
    gemm_tf32<<<dim3(DM / 128, ROWS / 128), 256, GEMM_SMEM>>>(
        attn, woutT, out, DM, DM);
}

// round 8
// speedup vs baseline: 3.8301x; 1.1343x over previous
#include <cuda_runtime.h>
#include <cstdint>
#include <math.h>

#define T_SEQ    2048
#define B_BATCH  2
#define DM       1024
#define NHEAD    16
#define HDIM     64
#define ROWS     (B_BATCH * T_SEQ)      // 4096
#define QKV_COLS (3 * DM)               // 3072

// Scratch (allocation-guard compliant: device globals)
__device__ float g_attn[(size_t)ROWS * DM];          // 16 MB (tf32-rounded)
__device__ float g_x32[(size_t)ROWS * DM];           // 16 MB  x pre-rounded
__device__ float g_WqkvT[(size_t)QKV_COLS * DM];     // 12 MB  [N][K] tf32
__device__ float g_WoutT[(size_t)DM * DM];           // 4 MB   [N][K] tf32
__device__ float g_rope_tab[(size_t)T_SEQ * 32 * 2]; // 512 KB (sin,cos)
// Packed per-head tf32 tensors [b][h][t][64]
__device__ float g_qpk[(size_t)ROWS * DM];           // 16 MB (pre-scaled 1/8)
__device__ float g_kpk[(size_t)ROWS * DM];           // 16 MB
__device__ float g_vpk[(size_t)ROWS * DM];           // 16 MB

__device__ __forceinline__ uint32_t f2tf32(float x) {
    uint32_t r;
    asm("cvt.rna.tf32.f32 %0, %1;" : "=r"(r) : "f"(x));
    return r;
}
__device__ __forceinline__ float f2tf32f(float x) {
    return __uint_as_float(f2tf32(x));
}
__device__ __forceinline__ uint32_t smem_u32(const void* p) {
    uint32_t a;
    asm("{ .reg .u64 t; cvta.to.shared.u64 t, %1; cvt.u32.u64 %0, t; }"
        : "=r"(a) : "l"(p));
    return a;
}
__device__ __forceinline__ void cp16(uint32_t dst, const void* src) {
    asm volatile("cp.async.cg.shared.global [%0], [%1], 16;"
                 :: "r"(dst), "l"(src));
}
#define CP_COMMIT() asm volatile("cp.async.commit_group;" ::: "memory")
#define CP_WAIT2()  asm volatile("cp.async.wait_group 2;" ::: "memory")
#define CP_WAIT1()  asm volatile("cp.async.wait_group 1;" ::: "memory")
#define CP_WAIT0()  asm volatile("cp.async.wait_group 0;" ::: "memory")

__device__ __forceinline__ void mma_tf32(
    float* c, uint32_t a0, uint32_t a1, uint32_t a2, uint32_t a3,
    uint32_t b0, uint32_t b1)
{
    asm volatile(
        "mma.sync.aligned.m16n8k8.row.col.f32.tf32.tf32.f32 "
        "{%0,%1,%2,%3}, {%4,%5,%6,%7}, {%8,%9}, {%0,%1,%2,%3};"
        : "+f"(c[0]), "+f"(c[1]), "+f"(c[2]), "+f"(c[3])
        : "r"(a0), "r"(a1), "r"(a2), "r"(a3), "r"(b0), "r"(b1));
}
__device__ __forceinline__ void ldsm_x4(
    uint32_t& r0, uint32_t& r1, uint32_t& r2, uint32_t& r3, uint32_t addr)
{
    asm volatile("ldmatrix.sync.aligned.m8n8.x4.shared.b16 {%0,%1,%2,%3}, [%4];"
                 : "=r"(r0), "=r"(r1), "=r"(r2), "=r"(r3) : "r"(addr));
}
__device__ __forceinline__ void ldsm_x2(
    uint32_t& r0, uint32_t& r1, uint32_t addr)
{
    asm volatile("ldmatrix.sync.aligned.m8n8.x2.shared.b16 {%0,%1}, [%2];"
                 : "=r"(r0), "=r"(r1) : "r"(addr));
}

// ===========================================================================
// Transpose + tf32 round: src [R][C] -> dst [C][R]
// ===========================================================================
__global__ void transpose_kernel(const float* __restrict__ src,
                                 float* __restrict__ dst, int R, int C)
{
    __shared__ float tile[32][33];
    int c0 = blockIdx.x * 32, r0 = blockIdx.y * 32;
    int x = threadIdx.x, y = threadIdx.y;   // 32 x 8
#pragma unroll
    for (int i = 0; i < 32; i += 8)
        tile[y + i][x] = f2tf32f(src[(size_t)(r0 + y + i) * C + c0 + x]);
    __syncthreads();
#pragma unroll
    for (int i = 0; i < 32; i += 8)
        dst[(size_t)(c0 + y + i) * R + r0 + x] = tile[x][y + i];
}

// x -> tf32-rounded copy
__global__ void convert_x_kernel(const float* __restrict__ x)
{
    int i = blockIdx.x * blockDim.x + threadIdx.x;
    float4 v = *(const float4*)(x + 4 * (size_t)i);
    float4 o = {f2tf32f(v.x), f2tf32f(v.y), f2tf32f(v.z), f2tf32f(v.w)};
    *(float4*)(g_x32 + 4 * (size_t)i) = o;
}

// ===========================================================================
// RoPE table
// ===========================================================================
__global__ void rope_table_kernel()
{
    int idx = blockIdx.x * blockDim.x + threadIdx.x;   // 65536
    if (idx >= T_SEQ * 32) return;
    int i = idx & 31;
    int t = idx >> 5;
    double ang = (double)t * pow(10000.0, -(double)i / 32.0);
    g_rope_tab[2 * idx + 0] = (float)sin(ang);
    g_rope_tab[2 * idx + 1] = (float)cos(ang);
}

// ===========================================================================
// Shared tf32 GEMM mainloop: 128x128 block, BK=16, 4-stage cp.async,
// ldmatrix fragment loads. Operands pre-rounded tf32.
// ===========================================================================
#define SST 20
#define NSTG 4
#define STG_FLOATS (128 * SST)
#define GEMM_SMEM (NSTG * 2 * STG_FLOATS * 4)   // 81920 B

__device__ __forceinline__ void gemm_mainloop(
    const float* __restrict__ A, const float* __restrict__ Bt,
    int K, int bm, int bn, float acc[4][4][4], uint32_t* sm)
{
    const int tid  = threadIdx.x;
    const int lane = tid & 31;
    const int wid  = tid >> 5;
    const int wm   = (wid >> 2) * 64;
    const int wn   = (wid & 3) * 32;

    uint32_t* As = sm;
    uint32_t* Bs = sm + NSTG * STG_FLOATS;
    const uint32_t as0 = smem_u32(As);
    const uint32_t bs0 = smem_u32(Bs);
    const int r0 = tid >> 2, c4 = (tid & 3) * 4;

    // ldmatrix per-lane address offsets (bytes)
    // A (x4): m = lane>>3; row += (m&1)*8 + lane&7; col += (m>>1)*4
    const uint32_t a_lane = (uint32_t)((((lane >> 3) & 1) * 8 + (lane & 7)) * SST * 4
                                       + (lane >> 4) * 16);
    // B (x2): row += lane&7; col += ((lane>>3)&1)*4
    const uint32_t b_lane = (uint32_t)((lane & 7) * SST * 4
                                       + ((lane >> 3) & 1) * 16);

    auto issue = [&](int ch) {
        const int s  = ch & (NSTG - 1);
        const int k0 = ch << 4;
        const uint32_t ao = as0 + (uint32_t)(s * STG_FLOATS + r0 * SST + c4) * 4;
        const uint32_t bo = bs0 + (uint32_t)(s * STG_FLOATS + r0 * SST + c4) * 4;
        cp16(ao,                A  + (size_t)(bm + r0)      * K + k0 + c4);
        cp16(ao + 64 * SST * 4, A  + (size_t)(bm + r0 + 64) * K + k0 + c4);
        cp16(bo,                Bt + (size_t)(bn + r0)      * K + k0 + c4);
        cp16(bo + 64 * SST * 4, Bt + (size_t)(bn + r0 + 64) * K + k0 + c4);
        CP_COMMIT();
    };

    const int niter = K >> 4;
    issue(0); issue(1); issue(2);

    for (int it = 0; it < niter; it++) {
        CP_WAIT2();
        __syncthreads();
        if (it + 3 < niter) issue(it + 3);

        const uint32_t abase = as0 + (uint32_t)((it & (NSTG - 1)) * STG_FLOATS) * 4;
        const uint32_t bbase = bs0 + (uint32_t)((it & (NSTG - 1)) * STG_FLOATS) * 4;

#pragma unroll
        for (int ks = 0; ks < 16; ks += 8) {
            uint32_t afr[4][4], bfr[4][2];
#pragma unroll
            for (int mt = 0; mt < 4; mt++) {
                const uint32_t ad = abase
                    + (uint32_t)(((wm + mt * 16) * SST + ks) * 4) + a_lane;
                ldsm_x4(afr[mt][0], afr[mt][1], afr[mt][2], afr[mt][3], ad);
            }
#pragma unroll
            for (int nt = 0; nt < 4; nt++) {
                const uint32_t bd = bbase
                    + (uint32_t)(((wn + nt * 8) * SST + ks) * 4) + b_lane;
                ldsm_x2(bfr[nt][0], bfr[nt][1], bd);
            }
#pragma unroll
            for (int mt = 0; mt < 4; mt++)
#pragma unroll
                for (int nt = 0; nt < 4; nt++)
                    mma_tf32(acc[mt][nt], afr[mt][0], afr[mt][1], afr[mt][2],
                             afr[mt][3], bfr[nt][0], bfr[nt][1]);
        }
    }
}

// ---------------------------------------------------------------------------
// QKV GEMM with fused RoPE + per-head pack epilogue.
// ---------------------------------------------------------------------------
__global__ __launch_bounds__(256, 2) void gemm_qkv_fused(
    const float* __restrict__ A, const float* __restrict__ Bt, int K)
{
    extern __shared__ uint32_t sm[];
    const int tid  = threadIdx.x;
    const int lane = tid & 31;
    const int wid  = tid >> 5;
    const int wm   = (wid >> 2) * 64;
    const int wn   = (wid & 3) * 32;
    const int bm   = blockIdx.y * 128;
    const int bn   = blockIdx.x * 128;
    const int gid  = lane >> 2;
    const int tig  = lane & 3;

    float acc[4][4][4];
#pragma unroll
    for (int i = 0; i < 4; i++)
#pragma unroll
        for (int j = 0; j < 4; j++)
#pragma unroll
            for (int q = 0; q < 4; q++) acc[i][j][q] = 0.0f;

    gemm_mainloop(A, Bt, K, bm, bn, acc, sm);

#pragma unroll
    for (int mt = 0; mt < 4; mt++) {
        const int rb = bm + wm + mt * 16 + gid;
#pragma unroll
        for (int nt = 0; nt < 4; nt++) {
            const int c  = bn + wn + nt * 8 + 2 * tig;
            const int region = c >> 10;
            const int cc = c & 1023;
            const int h  = cc >> 6;
            const int d  = cc & 63;
            const int i2 = d >> 1;
#pragma unroll
            for (int half = 0; half < 2; half++) {
                const int r = rb + half * 8;
                const int t = r & (T_SEQ - 1);
                const int b = r >> 11;
                const float a0 = acc[mt][nt][2 * half + 0];
                const float a1 = acc[mt][nt][2 * half + 1];
                const size_t dst =
                    ((size_t)(b * NHEAD + h) * T_SEQ + t) * HDIM + d;
                if (region == 2) {
                    float2 o = {f2tf32f(a0), f2tf32f(a1)};
                    *(float2*)&g_vpk[dst] = o;
                } else {
                    const float sn = g_rope_tab[2 * (t * 32 + i2) + 0];
                    const float cs = g_rope_tab[2 * (t * 32 + i2) + 1];
                    float o0 = a0 * cs - a1 * sn;
                    float o1 = a1 * cs + a0 * sn;
                    if (region == 0) {
                        float2 o = {f2tf32f(o0 * 0.125f), f2tf32f(o1 * 0.125f)};
                        *(float2*)&g_qpk[dst] = o;
                    } else {
                        float2 o = {f2tf32f(o0), f2tf32f(o1)};
                        *(float2*)&g_kpk[dst] = o;
                    }
                }
            }
        }
    }
}

// ---------------------------------------------------------------------------
// Plain tf32 GEMM (output projection)
// ---------------------------------------------------------------------------
__global__ __launch_bounds__(256, 2) void gemm_tf32(
    const float* __restrict__ A, const float* __restrict__ Bt,
    float* __restrict__ C, int N, int K)
{
    extern __shared__ uint32_t sm[];
    const int tid  = threadIdx.x;
    const int lane = tid & 31;
    const int wid  = tid >> 5;
    const int wm   = (wid >> 2) * 64;
    const int wn   = (wid & 3) * 32;
    const int bm   = blockIdx.y * 128;
    const int bn   = blockIdx.x * 128;
    const int gid  = lane >> 2;
    const int tig  = lane & 3;

    float acc[4][4][4];
#pragma unroll
    for (int i = 0; i < 4; i++)
#pragma unroll
        for (int j = 0; j < 4; j++)
#pragma unroll
            for (int q = 0; q < 4; q++) acc[i][j][q] = 0.0f;

    gemm_mainloop(A, Bt, K, bm, bn, acc, sm);

#pragma unroll
    for (int mt = 0; mt < 4; mt++) {
        const int rb = bm + wm + mt * 16;
#pragma unroll
        for (int nt = 0; nt < 4; nt++) {
            const int cb = bn + wn + nt * 8 + 2 * tig;
            float2 lo = {acc[mt][nt][0], acc[mt][nt][1]};
            float2 hi = {acc[mt][nt][2], acc[mt][nt][3]};
            *(float2*)(C + (size_t)(rb + gid)     * N + cb) = lo;
            *(float2*)(C + (size_t)(rb + gid + 8) * N + cb) = hi;
        }
    }
}

// ===========================================================================
// Tensor-core causal flash attention.
// K/P/Q smem stride 68 (conflict-free row loads + LDSM); V stride 72
// (conflict-free transposed loads). ldmatrix for K and P fragments.
// ===========================================================================
#define SKP 68
#define SV  72
#define FA_SMEM ((2 * 64 * SKP + 2 * 64 * SV + 128 * SKP) * 4)

__global__ __launch_bounds__(256) void flash_attn_tc()
{
    extern __shared__ uint32_t smu[];
    uint32_t* Ksm = smu;                       // [2][key][d]  stride 68
    uint32_t* Vsm = Ksm + 2 * 64 * SKP;        // [2][key][d]  stride 72
    uint32_t* Psm = Vsm + 2 * 64 * SV;         // [m][key]     stride 68

    const int tid  = threadIdx.x;
    const int lane = tid & 31;
    const int wid  = tid >> 5;
    const int gid  = lane >> 2;
    const int tig  = lane & 3;
    const int qi = (int)(gridDim.x - 1 - blockIdx.x);
    const int h = blockIdx.y, b = blockIdx.z;
    const int qbase = qi * 128;
    const int bh = b * NHEAD + h;
    const int wrow = 16 * wid;

    const uint32_t ksm0 = smem_u32(Ksm);
    const uint32_t vsm0 = smem_u32(Vsm);
    const uint32_t psm0 = smem_u32(Psm);
    const float* kbase_p = g_kpk + (size_t)bh * T_SEQ * HDIM;
    const float* vbase_p = g_vpk + (size_t)bh * T_SEQ * HDIM;

    // ldmatrix lane offsets (bytes)
    // K (x4, 2 k-steps): row += lane&7 ; col += (lane>>3)*4
    const uint32_t k_lane = (uint32_t)((lane & 7) * SKP * 4 + (lane >> 3) * 16);
    // P (x4 A-frag): row += ((lane>>3)&1)*8 + lane&7 ; col += (lane>>4)*4
    const uint32_t p_lane = (uint32_t)((((lane >> 3) & 1) * 8 + (lane & 7)) * SKP * 4
                                       + (lane >> 4) * 16);

    auto issue_kv = [&](int kt, int st) {
        const int n = tid >> 2;
        const int c = (tid & 3) * 16;
        const size_t go = (size_t)(kt * 64 + n) * HDIM + c;
        const uint32_t ko = (uint32_t)(st * 64 * SKP + n * SKP + c) * 4;
        const uint32_t vo = (uint32_t)(st * 64 * SV  + n * SV  + c) * 4;
#pragma unroll
        for (int j = 0; j < 4; j++) {
            cp16(ksm0 + ko + j * 16, kbase_p + go + j * 4);
            cp16(vsm0 + vo + j * 16, vbase_p + go + j * 4);
        }
    };

    // stage Q (tf32, pre-scaled) into Psm
    {
        int m = tid >> 1;
        int d0 = (tid & 1) * 32;
        const float* src = g_qpk + ((size_t)bh * T_SEQ + qbase + m) * HDIM + d0;
#pragma unroll
        for (int j = 0; j < 8; j++) {
            uint4 v = *(const uint4*)(src + 4 * j);
            *(uint4*)&Psm[m * SKP + d0 + 4 * j] = v;
        }
    }

    const int nkt = qbase / 64 + 2;
    issue_kv(0, 0);
    CP_COMMIT();
    __syncthreads();

    // hoist Q fragments via ldmatrix
    uint32_t qf[8][4];
#pragma unroll
    for (int ks = 0; ks < 8; ks++) {
        const uint32_t qa = psm0 + (uint32_t)((wrow * SKP + ks * 8) * 4) + p_lane;
        ldsm_x4(qf[ks][0], qf[ks][1], qf[ks][2], qf[ks][3], qa);
    }

    float Oacc[8][4];
#pragma unroll
    for (int nt = 0; nt < 8; nt++)
#pragma unroll
        for (int q = 0; q < 4; q++) Oacc[nt][q] = 0.0f;
    float mrow0 = -1e30f, mrow1 = -1e30f, lrow0 = 0.0f, lrow1 = 0.0f;

    for (int kt = 0; kt < nkt; kt++) {
        const int st = kt & 1;
        const int kb = kt * 64;
        const bool more = (kt + 1) < nkt;
        if (more) { issue_kv(kt + 1, st ^ 1); CP_COMMIT(); }
        if (more) { CP_WAIT1(); } else { CP_WAIT0(); }
        __syncthreads();

        const uint32_t kst = ksm0 + (uint32_t)(st * 64 * SKP * 4);
        const uint32_t* Vst = Vsm + st * 64 * SV;

        // ---- S = Q @ K^T ----
        float sacc[8][4];
#pragma unroll
        for (int nt = 0; nt < 8; nt++)
#pragma unroll
            for (int q = 0; q < 4; q++) sacc[nt][q] = 0.0f;

#pragma unroll
        for (int kp = 0; kp < 4; kp++) {      // pairs of k-steps
#pragma unroll
            for (int nt = 0; nt < 8; nt++) {
                uint32_t b0, b1, b2, b3;      // (b0,b1)=ks even, (b2,b3)=ks odd
                const uint32_t ka = kst
                    + (uint32_t)((nt * 8 * SKP + kp * 16) * 4) + k_lane;
                ldsm_x4(b0, b1, b2, b3, ka);
                mma_tf32(sacc[nt], qf[2 * kp][0], qf[2 * kp][1],
                         qf[2 * kp][2], qf[2 * kp][3], b0, b1);
                mma_tf32(sacc[nt], qf[2 * kp + 1][0], qf[2 * kp + 1][1],
                         qf[2 * kp + 1][2], qf[2 * kp + 1][3], b2, b3);
            }
        }

        // ---- causal mask ----
        const int r0g = qbase + wrow + gid;
        if (kb + 63 > qbase) {
#pragma unroll
            for (int nt = 0; nt < 8; nt++) {
                int col = kb + nt * 8 + 2 * tig;
                if (col     > r0g)     sacc[nt][0] = -1e30f;
                if (col + 1 > r0g)     sacc[nt][1] = -1e30f;
                if (col     > r0g + 8) sacc[nt][2] = -1e30f;
                if (col + 1 > r0g + 8) sacc[nt][3] = -1e30f;
            }
        }

        // ---- online softmax ----
        float mx0 = -1e30f, mx1 = -1e30f;
#pragma unroll
        for (int nt = 0; nt < 8; nt++) {
            mx0 = fmaxf(mx0, fmaxf(sacc[nt][0], sacc[nt][1]));
            mx1 = fmaxf(mx1, fmaxf(sacc[nt][2], sacc[nt][3]));
        }
        mx0 = fmaxf(mx0, __shfl_xor_sync(0xffffffffu, mx0, 1));
        mx0 = fmaxf(mx0, __shfl_xor_sync(0xffffffffu, mx0, 2));
        mx1 = fmaxf(mx1, __shfl_xor_sync(0xffffffffu, mx1, 1));
        mx1 = fmaxf(mx1, __shfl_xor_sync(0xffffffffu, mx1, 2));
        const float nm0 = fmaxf(mrow0, mx0);
        const float nm1 = fmaxf(mrow1, mx1);

        float sum0 = 0.0f, sum1 = 0.0f;
#pragma unroll
        for (int nt = 0; nt < 8; nt++) {
            float p00 = __expf(sacc[nt][0] - nm0);
            float p01 = __expf(sacc[nt][1] - nm0);
            float p10 = __expf(sacc[nt][2] - nm1);
            float p11 = __expf(sacc[nt][3] - nm1);
            sum0 += p00 + p01;
            sum1 += p10 + p11;
            uint2 u0 = {f2tf32(p00), f2tf32(p01)};
            uint2 u1 = {f2tf32(p10), f2tf32(p11)};
            *(uint2*)&Psm[(wrow + gid)     * SKP + nt * 8 + 2 * tig] = u0;
            *(uint2*)&Psm[(wrow + gid + 8) * SKP + nt * 8 + 2 * tig] = u1;
        }
        sum0 += __shfl_xor_sync(0xffffffffu, sum0, 1);
        sum0 += __shfl_xor_sync(0xffffffffu, sum0, 2);
        sum1 += __shfl_xor_sync(0xffffffffu, sum1, 1);
        sum1 += __shfl_xor_sync(0xffffffffu, sum1, 2);

        const float a0 = __expf(mrow0 - nm0);
        const float a1 = __expf(mrow1 - nm1);
        lrow0 = lrow0 * a0 + sum0;
        lrow1 = lrow1 * a1 + sum1;
        mrow0 = nm0; mrow1 = nm1;
#pragma unroll
        for (int nt = 0; nt < 8; nt++) {
            Oacc[nt][0] *= a0; Oacc[nt][1] *= a0;
            Oacc[nt][2] *= a1; Oacc[nt][3] *= a1;
        }
        __syncwarp();

        // ---- O += P @ V ----
#pragma unroll
        for (int ks = 0; ks < 8; ks++) {
            uint32_t a0f, a1f, a2f, a3f;
            const uint32_t pa = psm0
                + (uint32_t)((wrow * SKP + ks * 8) * 4) + p_lane;
            ldsm_x4(a0f, a1f, a2f, a3f, pa);
#pragma unroll
            for (int nt = 0; nt < 8; nt++) {
                uint32_t b0 = Vst[(ks * 8 + tig)     * SV + nt * 8 + gid];
                uint32_t b1 = Vst[(ks * 8 + tig + 4) * SV + nt * 8 + gid];
                mma_tf32(Oacc[nt], a0f, a1f, a2f, a3f, b0, b1);
            }
        }
        __syncthreads();
    }

    const float i0 = 1.0f / lrow0;
    const float i1 = 1.0f / lrow1;
    const int r0g = qbase + wrow + gid;
#pragma unroll
    for (int nt = 0; nt < 8; nt++) {
        const int c = h * HDIM + nt * 8 + 2 * tig;
        float2 lo = {f2tf32f(Oacc[nt][0] * i0), f2tf32f(Oacc[nt][1] * i0)};
        float2 hi = {f2tf32f(Oacc[nt][2] * i1), f2tf32f(Oacc[nt][3] * i1)};
        *(float2*)&g_attn[((size_t)b * T_SEQ + r0g)     * DM + c] = lo;
        *(float2*)&g_attn[((size_t)b * T_SEQ + r0g + 8) * DM + c] = hi;
    }
}

// ===========================================================================
extern "C" void kernel_launch(void* const* d_in, const int* in_sizes, int n_in,
                              void* d_out, int out_size)
{
    const float* x    = (const float*)d_in[0];
    const float* Wqkv = (const float*)d_in[1];
    const float* Wout = (const float*)d_in[2];
    float* out = (float*)d_out;

    float *attn = nullptr, *wqkvT = nullptr, *woutT = nullptr, *x32 = nullptr;
    cudaGetSymbolAddress((void**)&attn,  g_attn);
    cudaGetSymbolAddress((void**)&wqkvT, g_WqkvT);
    cudaGetSymbolAddress((void**)&woutT, g_WoutT);
    cudaGetSymbolAddress((void**)&x32,   g_x32);

    cudaFuncSetAttribute(gemm_qkv_fused,
                         cudaFuncAttributeMaxDynamicSharedMemorySize, GEMM_SMEM);
    cudaFuncSetAttribute(gemm_tf32,
                         cudaFuncAttributeMaxDynamicSharedMemorySize, GEMM_SMEM);
    cudaFuncSetAttribute(flash_attn_tc,
                         cudaFuncAttributeMaxDynamicSharedMemorySize, FA_SMEM);

    // 0) RoPE table, weight transposes (+tf32 round), x round
    rope_table_kernel<<<(T_SEQ * 32 + 255) / 256, 256>>>();
    transpose_kernel<<<dim3(QKV_COLS / 32, DM / 32), dim3(32, 8)>>>(
        Wqkv, wqkvT, DM, QKV_COLS);
    transpose_kernel<<<dim3(DM / 32, DM / 32), dim3(32, 8)>>>(
        Wout, woutT, DM, DM);
    convert_x_kernel<<<(ROWS * DM / 4) / 256, 256>>>(x);

    // 1) QKV projection + fused RoPE + per-head pack
    gemm_qkv_fused<<<dim3(QKV_COLS / 128, ROWS / 128), 256, GEMM_SMEM>>>(
        x32, wqkvT, DM);

    // 2) Causal flash attention
    flash_attn_tc<<<dim3(T_SEQ / 128, NHEAD, B_BATCH), 256, FA_SMEM>>>();

    // 3) Output projection
    gemm_tf32<<<dim3(DM / 128, ROWS / 128), 256, GEMM_SMEM>>>(
        attn, woutT, out, DM, DM);
}